// round 1
// baseline (speedup 1.0000x reference)
#include <cuda_runtime.h>
#include <math.h>

#define TOKENS 4096
#define HD 768
#define ID 3072
#define NE 7
#define TOPK 2
#define NA (TOKENS * TOPK)   // 8192 assignments

// ---------------- device scratch (static, no allocation) ----------------
__device__ int   d_counts[NE];
__device__ int   d_offsets[NE + 1];
__device__ int   d_cursor[NE];
__device__ int   d_tkExpert[NA];
__device__ float d_tkProb[NA];
__device__ int   d_rowToken[NA];
__device__ float d_rowProb[NA];
__device__ float d_h1[(size_t)NA * ID];   // 96 MB intermediate activations

// ---------------- small utility kernels ----------------
__global__ void reset_counters_kernel() {
    int i = threadIdx.x;
    if (i < NE) { d_counts[i] = 0; d_cursor[i] = 0; }
}

__global__ void zero_out_kernel(float* out, int n) {
    int i = blockIdx.x * blockDim.x + threadIdx.x;
    if (i < n) out[i] = 0.0f;
}

// ---------------- gate: logits, top-2 softmax, assignment build ----------------
__global__ void gate_kernel(const float* __restrict__ x,
                            const float* __restrict__ gW,
                            const float* __restrict__ gb,
                            float* __restrict__ out_gw) {
    int t = blockIdx.x;
    __shared__ float logits[NE];
    int w = threadIdx.x >> 5;
    int lane = threadIdx.x & 31;
    const float* xr = x + (size_t)t * HD;
    if (w < NE) {
        const float* wr = gW + (size_t)w * HD;
        float s = 0.0f;
        for (int h = lane; h < HD; h += 32) s += xr[h] * wr[h];
        #pragma unroll
        for (int o = 16; o; o >>= 1) s += __shfl_down_sync(0xffffffffu, s, o);
        if (lane == 0) logits[w] = s + gb[w];
    }
    __syncthreads();
    if (threadIdx.x == 0) {
        int i0 = 0;
        #pragma unroll
        for (int e = 1; e < NE; e++) if (logits[e] > logits[i0]) i0 = e;
        int i1 = -1;
        #pragma unroll
        for (int e = 0; e < NE; e++) {
            if (e == i0) continue;
            if (i1 < 0 || logits[e] > logits[i1]) i1 = e;
        }
        float v0 = logits[i0], v1 = logits[i1];
        float e1 = expf(v1 - v0);
        float inv = 1.0f / (1.0f + e1);
        float p0 = inv;
        float p1 = e1 * inv;
        float* gw = out_gw + (size_t)t * NE;
        #pragma unroll
        for (int e = 0; e < NE; e++) gw[e] = 0.0f;
        gw[i0] = p0; gw[i1] = p1;
        d_tkExpert[t * 2 + 0] = i0; d_tkProb[t * 2 + 0] = p0;
        d_tkExpert[t * 2 + 1] = i1; d_tkProb[t * 2 + 1] = p1;
        atomicAdd(&d_counts[i0], 1);
        atomicAdd(&d_counts[i1], 1);
    }
}

__global__ void offsets_kernel() {
    // single thread exclusive scan over 7 counts
    int acc = 0;
    for (int e = 0; e < NE; e++) { d_offsets[e] = acc; acc += d_counts[e]; }
    d_offsets[NE] = acc;
}

__global__ void scatter_kernel() {
    int a = blockIdx.x * blockDim.x + threadIdx.x;
    if (a >= NA) return;
    int e = d_tkExpert[a];
    int pos = d_offsets[e] + atomicAdd(&d_cursor[e], 1);
    d_rowToken[pos] = a >> 1;
    d_rowProb[pos]  = d_tkProb[a];
}

// ---------------- GEMM1: H1[row, ID] = gelu(x[tok] @ W1[e] + b1[e]) ----------------
// block tile 64(M) x 64(N), K-tile 16, 256 threads, 4x4 per-thread micro-tile
__global__ void __launch_bounds__(256)
gemm1_kernel(const float* __restrict__ x,
             const float* __restrict__ W1,
             const float* __restrict__ b1) {
    int e = blockIdx.z;
    int cnt = d_counts[e];
    int rowTile = blockIdx.y * 64;
    if (rowTile >= cnt) return;
    int base = d_offsets[e];
    int n0 = blockIdx.x * 64;

    __shared__ float As[16][64];
    __shared__ float Bs[16][64];
    __shared__ int   stok[64];

    int tid = threadIdx.x;
    if (tid < 64) {
        int r = rowTile + tid;
        stok[tid] = (r < cnt) ? d_rowToken[base + r] : -1;
    }
    __syncthreads();

    int tx = tid & 15, ty = tid >> 4;
    int ar = tid >> 2;            // 0..63 : A row within tile
    int ak = (tid & 3) * 4;       // 0,4,8,12 : A k offset
    int bk = tid >> 4;            // 0..15 : B k row
    int bn = (tid & 15) * 4;      // B n offset
    int tok = stok[ar];
    const float* Wb = W1 + (size_t)e * HD * ID;

    float acc[4][4] = {};

    for (int k0 = 0; k0 < HD; k0 += 16) {
        float4 av = make_float4(0.f, 0.f, 0.f, 0.f);
        if (tok >= 0)
            av = *reinterpret_cast<const float4*>(x + (size_t)tok * HD + k0 + ak);
        As[ak + 0][ar] = av.x; As[ak + 1][ar] = av.y;
        As[ak + 2][ar] = av.z; As[ak + 3][ar] = av.w;

        *reinterpret_cast<float4*>(&Bs[bk][bn]) =
            *reinterpret_cast<const float4*>(Wb + (size_t)(k0 + bk) * ID + n0 + bn);
        __syncthreads();

        #pragma unroll
        for (int kk = 0; kk < 16; kk++) {
            float4 a = *reinterpret_cast<float4*>(&As[kk][ty * 4]);
            float4 b = *reinterpret_cast<float4*>(&Bs[kk][tx * 4]);
            float ai[4] = {a.x, a.y, a.z, a.w};
            float bj[4] = {b.x, b.y, b.z, b.w};
            #pragma unroll
            for (int i = 0; i < 4; i++)
                #pragma unroll
                for (int j = 0; j < 4; j++)
                    acc[i][j] += ai[i] * bj[j];
        }
        __syncthreads();
    }

    const float* bb = b1 + (size_t)e * ID;
    #pragma unroll
    for (int i = 0; i < 4; i++) {
        int r = rowTile + ty * 4 + i;
        if (r >= cnt) break;
        float* hrow = d_h1 + (size_t)(base + r) * ID;
        #pragma unroll
        for (int j = 0; j < 4; j++) {
            int n = n0 + tx * 4 + j;
            float v = acc[i][j] + bb[n];
            // exact gelu
            float g = 0.5f * v * (1.0f + erff(v * 0.70710678118654752f));
            hrow[n] = g;
        }
    }
}

// ---------------- GEMM2: out[tok] += p * (H1[row] @ W2[e] + b2[e]) ----------------
__global__ void __launch_bounds__(256)
gemm2_kernel(const float* __restrict__ W2,
             const float* __restrict__ b2,
             float* __restrict__ out) {
    int e = blockIdx.z;
    int cnt = d_counts[e];
    int rowTile = blockIdx.y * 64;
    if (rowTile >= cnt) return;
    int base = d_offsets[e];
    int n0 = blockIdx.x * 64;

    __shared__ float As[16][64];
    __shared__ float Bs[16][64];

    int tid = threadIdx.x;
    int tx = tid & 15, ty = tid >> 4;
    int ar = tid >> 2;
    int ak = (tid & 3) * 4;
    int bk = tid >> 4;
    int bn = (tid & 15) * 4;

    int arow = rowTile + ar;
    bool arow_ok = (arow < cnt);
    const float* Arow = d_h1 + (size_t)(base + (arow_ok ? arow : 0)) * ID;
    const float* Wb = W2 + (size_t)e * ID * HD;

    float acc[4][4] = {};

    for (int k0 = 0; k0 < ID; k0 += 16) {
        float4 av = make_float4(0.f, 0.f, 0.f, 0.f);
        if (arow_ok)
            av = *reinterpret_cast<const float4*>(Arow + k0 + ak);
        As[ak + 0][ar] = av.x; As[ak + 1][ar] = av.y;
        As[ak + 2][ar] = av.z; As[ak + 3][ar] = av.w;

        *reinterpret_cast<float4*>(&Bs[bk][bn]) =
            *reinterpret_cast<const float4*>(Wb + (size_t)(k0 + bk) * HD + n0 + bn);
        __syncthreads();

        #pragma unroll
        for (int kk = 0; kk < 16; kk++) {
            float4 a = *reinterpret_cast<float4*>(&As[kk][ty * 4]);
            float4 b = *reinterpret_cast<float4*>(&Bs[kk][tx * 4]);
            float ai[4] = {a.x, a.y, a.z, a.w};
            float bj[4] = {b.x, b.y, b.z, b.w};
            #pragma unroll
            for (int i = 0; i < 4; i++)
                #pragma unroll
                for (int j = 0; j < 4; j++)
                    acc[i][j] += ai[i] * bj[j];
        }
        __syncthreads();
    }

    const float* bb = b2 + (size_t)e * HD;
    #pragma unroll
    for (int i = 0; i < 4; i++) {
        int r = rowTile + ty * 4 + i;
        if (r >= cnt) break;
        int tok = d_rowToken[base + r];
        float p = d_rowProb[base + r];
        float* orow = out + (size_t)tok * HD;
        #pragma unroll
        for (int j = 0; j < 4; j++) {
            int n = n0 + tx * 4 + j;
            atomicAdd(&orow[n], p * (acc[i][j] + bb[n]));
        }
    }
}

// ---------------- launch ----------------
extern "C" void kernel_launch(void* const* d_in, const int* in_sizes, int n_in,
                              void* d_out, int out_size) {
    const float* x     = (const float*)d_in[0];
    const float* gateW = (const float*)d_in[1];
    const float* gateB = (const float*)d_in[2];
    const float* W1    = (const float*)d_in[3];
    const float* b1    = (const float*)d_in[4];
    const float* W2    = (const float*)d_in[5];
    const float* b2    = (const float*)d_in[6];
    float* out = (float*)d_out;                    // [TOKENS*HD] output
    float* out_gw = out + (size_t)TOKENS * HD;     // [TOKENS*NE] gate weights

    reset_counters_kernel<<<1, 32>>>();
    zero_out_kernel<<<(TOKENS * HD + 255) / 256, 256>>>(out, TOKENS * HD);
    gate_kernel<<<TOKENS, 224>>>(x, gateW, gateB, out_gw);
    offsets_kernel<<<1, 1>>>();
    scatter_kernel<<<(NA + 255) / 256, 256>>>();

    dim3 g1(ID / 64, NA / 64, NE);   // (48, 128, 7)
    gemm1_kernel<<<g1, 256>>>(x, W1, b1);

    dim3 g2(HD / 64, NA / 64, NE);   // (12, 128, 7)
    gemm2_kernel<<<g2, 256>>>(W2, b2, out);
}

// round 5
// speedup vs baseline: 1.4567x; 1.4567x over previous
#include <cuda_runtime.h>
#include <cuda_bf16.h>
#include <cstdint>
#include <math.h>

#define TOKENS 4096
#define HD 768
#define ID 3072
#define NE 7
#define NA (TOKENS * 2)   // 8192 assignments (top-2)

// ---------------- device scratch (static, no allocation) ----------------
__device__ int   d_counts[NE];
__device__ int   d_offsets[NE + 1];
__device__ int   d_cursor[NE];
__device__ int   d_tkExpert[NA];
__device__ float d_tkProb[NA];
__device__ int   d_rowToken[NA];
__device__ float d_rowProb[NA];
__device__ float d_h1[(size_t)NA * ID];   // 96 MB fp32 intermediate

// ---------------- helpers ----------------
__device__ __forceinline__ void mma16816(float* c, const uint32_t* a,
                                         uint32_t b0, uint32_t b1) {
    asm volatile(
        "mma.sync.aligned.m16n8k16.row.col.f32.bf16.bf16.f32 "
        "{%0,%1,%2,%3}, {%4,%5,%6,%7}, {%8,%9}, {%0,%1,%2,%3};"
        : "+f"(c[0]), "+f"(c[1]), "+f"(c[2]), "+f"(c[3])
        : "r"(a[0]), "r"(a[1]), "r"(a[2]), "r"(a[3]), "r"(b0), "r"(b1));
}

__device__ __forceinline__ void split_bf(float v, __nv_bfloat16& h, __nv_bfloat16& l) {
    h = __float2bfloat16(v);
    l = __float2bfloat16(v - __bfloat162float(h));
}
__device__ __forceinline__ uint32_t pack_bf(__nv_bfloat16 a, __nv_bfloat16 b) {
    __nv_bfloat162 t; t.x = a; t.y = b;
    uint32_t r; memcpy(&r, &t, 4); return r;
}

// XOR swizzle on 8-element (16B) chunks within a 32-wide bf16 row.
__device__ __forceinline__ int swz(int row, int col) {
    return ((((col >> 3) ^ ((row >> 1) & 3)) & 3) << 3) | (col & 7);
}

// ---------------- small utility kernels ----------------
__global__ void reset_counters_kernel() {
    int i = threadIdx.x;
    if (i < NE) { d_counts[i] = 0; d_cursor[i] = 0; }
}

__global__ void zero_out_kernel(float* out, int n) {
    int i = blockIdx.x * blockDim.x + threadIdx.x;
    if (i < n) out[i] = 0.0f;
}

// ---------------- gate: logits, top-2 softmax, assignment build ----------------
__global__ void gate_kernel(const float* __restrict__ x,
                            const float* __restrict__ gW,
                            const float* __restrict__ gb,
                            float* __restrict__ out_gw) {
    int t = blockIdx.x;
    __shared__ float logits[NE];
    int w = threadIdx.x >> 5;
    int lane = threadIdx.x & 31;
    const float* xr = x + (size_t)t * HD;
    if (w < NE) {
        const float* wr = gW + (size_t)w * HD;
        float s = 0.0f;
        for (int h = lane; h < HD; h += 32) s += xr[h] * wr[h];
        #pragma unroll
        for (int o = 16; o; o >>= 1) s += __shfl_down_sync(0xffffffffu, s, o);
        if (lane == 0) logits[w] = s + gb[w];
    }
    __syncthreads();
    if (threadIdx.x == 0) {
        int i0 = 0;
        #pragma unroll
        for (int e = 1; e < NE; e++) if (logits[e] > logits[i0]) i0 = e;
        int i1 = -1;
        #pragma unroll
        for (int e = 0; e < NE; e++) {
            if (e == i0) continue;
            if (i1 < 0 || logits[e] > logits[i1]) i1 = e;
        }
        float v0 = logits[i0], v1 = logits[i1];
        float e1 = expf(v1 - v0);
        float inv = 1.0f / (1.0f + e1);
        float p0 = inv, p1 = e1 * inv;
        float* gw = out_gw + (size_t)t * NE;
        #pragma unroll
        for (int e = 0; e < NE; e++) gw[e] = 0.0f;
        gw[i0] = p0; gw[i1] = p1;
        d_tkExpert[t * 2 + 0] = i0; d_tkProb[t * 2 + 0] = p0;
        d_tkExpert[t * 2 + 1] = i1; d_tkProb[t * 2 + 1] = p1;
        atomicAdd(&d_counts[i0], 1);
        atomicAdd(&d_counts[i1], 1);
    }
}

__global__ void offsets_kernel() {
    int acc = 0;
    for (int e = 0; e < NE; e++) { d_offsets[e] = acc; acc += d_counts[e]; }
    d_offsets[NE] = acc;
}

__global__ void scatter_kernel() {
    int a = blockIdx.x * blockDim.x + threadIdx.x;
    if (a >= NA) return;
    int e = d_tkExpert[a];
    int pos = d_offsets[e] + atomicAdd(&d_cursor[e], 1);
    d_rowToken[pos] = a >> 1;
    d_rowProb[pos]  = d_tkProb[a];
}

// ---------------- HMMA mainloop (shared, unified) ----------------
// Block tile 256(M) x 64(N), k-tile 32. A (gathered fp32 rows) and B (fp32 W
// panel, [K][N] row-major) are loaded to registers, split to bf16 hi/lo into
// static smem once per k-tile, then consumed by mma.sync with 3-term
// compensation: Ahi*Bhi + Alo*Bhi + Ahi*Blo.
// 512 threads = 16 warps: 4 warps along M (64 rows each) x 4 warps along N (16).

template<int KDIM>
__device__ __forceinline__ void mainloop(
    const float* __restrict__ A,     // row source (x or h1), row stride KDIM
    const float* __restrict__ W,     // expert weight [KDIM][NDIM] row-major
    int NDIM, int n0,
    const int* arow,                 // smem: 256 absolute row indices into A
    __nv_bfloat16 (*sAhi)[32], __nv_bfloat16 (*sAlo)[32],
    __nv_bfloat16 (*sBhi)[32], __nv_bfloat16 (*sBlo)[32],
    float acc[4][2][4])
{
    constexpr int KT = KDIM / 32;
    int tid = threadIdx.x;
    int lane = tid & 31, warp = tid >> 5;
    int warpM = (warp >> 2) * 64;
    int warpN = (warp & 3) * 16;
    int qr = lane >> 2;          // fragment row-in-8
    int qc = (lane & 3) * 2;     // fragment k-pair base (even)

    // fill assignment
    int fr = tid >> 1;           // A row 0..255
    int fh = tid & 1;            // which 16-col half
    const float* aSrc = A + (size_t)arow[fr] * KDIM + fh * 16;
    int kr = tid & 31;           // B k row
    int ng = (tid >> 5) * 4;     // B n group (4 cols)
    const float* bSrc = W + (size_t)kr * NDIM + n0 + ng;

    float4 pa[4]; float4 pb;
    // preload k-tile 0
    #pragma unroll
    for (int q = 0; q < 4; q++) pa[q] = *(const float4*)(aSrc + q * 4);
    pb = *(const float4*)(bSrc);

    for (int kt = 0; kt < KT; kt++) {
        // ---- store prefetched regs -> split bf16 smem
        #pragma unroll
        for (int q = 0; q < 4; q++) {
            float v[4] = {pa[q].x, pa[q].y, pa[q].z, pa[q].w};
            #pragma unroll
            for (int j = 0; j < 2; j++) {
                int c = fh * 16 + q * 4 + j * 2;
                __nv_bfloat16 h0, l0, h1v, l1v;
                split_bf(v[j * 2],     h0, l0);
                split_bf(v[j * 2 + 1], h1v, l1v);
                int s = swz(fr, c);
                *(uint32_t*)&sAhi[fr][s] = pack_bf(h0, h1v);
                *(uint32_t*)&sAlo[fr][s] = pack_bf(l0, l1v);
            }
        }
        {
            float bv[4] = {pb.x, pb.y, pb.z, pb.w};
            #pragma unroll
            for (int i = 0; i < 4; i++) {
                __nv_bfloat16 h0, l0;
                split_bf(bv[i], h0, l0);
                int s = swz(ng + i, kr);
                sBhi[ng + i][s] = h0;
                sBlo[ng + i][s] = l0;
            }
        }
        __syncthreads();

        // ---- prefetch next k-tile
        if (kt + 1 < KT) {
            const float* an = aSrc + (kt + 1) * 32;
            #pragma unroll
            for (int q = 0; q < 4; q++) pa[q] = *(const float4*)(an + q * 4);
            pb = *(const float4*)(bSrc + (size_t)(kt + 1) * 32 * NDIM);
        }

        // ---- compute
        #pragma unroll
        for (int kk = 0; kk < 2; kk++) {
            uint32_t ah[4][4], al[4][4], bh[2][2], bl[2][2];
            #pragma unroll
            for (int mi = 0; mi < 4; mi++) {
                #pragma unroll
                for (int j = 0; j < 4; j++) {
                    int row = warpM + mi * 16 + (j & 1) * 8 + qr;
                    int col = kk * 16 + (j >> 1) * 8 + qc;
                    int s = swz(row, col);
                    ah[mi][j] = *(const uint32_t*)&sAhi[row][s];
                    al[mi][j] = *(const uint32_t*)&sAlo[row][s];
                }
            }
            #pragma unroll
            for (int ni = 0; ni < 2; ni++) {
                #pragma unroll
                for (int j = 0; j < 2; j++) {
                    int n = warpN + ni * 8 + qr;
                    int col = kk * 16 + j * 8 + qc;
                    int s = swz(n, col);
                    bh[ni][j] = *(const uint32_t*)&sBhi[n][s];
                    bl[ni][j] = *(const uint32_t*)&sBlo[n][s];
                }
            }
            #pragma unroll
            for (int mi = 0; mi < 4; mi++) {
                #pragma unroll
                for (int ni = 0; ni < 2; ni++) {
                    mma16816(acc[mi][ni], ah[mi], bh[ni][0], bh[ni][1]);
                    mma16816(acc[mi][ni], al[mi], bh[ni][0], bh[ni][1]);
                    mma16816(acc[mi][ni], ah[mi], bl[ni][0], bl[ni][1]);
                }
            }
        }
        __syncthreads();
    }
}

// ===================== GEMM1: h1 = gelu(x @ W1 + b1) ==========================
__global__ void __launch_bounds__(512)
gemm1_hmma(const float* __restrict__ x,
           const float* __restrict__ W1,
           const float* __restrict__ b1) {
    int e = blockIdx.z;
    int cnt = d_counts[e];
    int rowTile = blockIdx.y * 256;
    if (rowTile >= cnt) return;
    int base = d_offsets[e];
    int n0 = blockIdx.x * 64;

    __shared__ __nv_bfloat16 sAhi[256][32], sAlo[256][32];
    __shared__ __nv_bfloat16 sBhi[64][32],  sBlo[64][32];
    __shared__ int arow[256];

    int tid = threadIdx.x;
    if (tid < 256) {
        int r = rowTile + tid;
        arow[tid] = d_rowToken[base + min(r, cnt - 1)];
    }
    __syncthreads();

    float acc[4][2][4] = {};
    mainloop<HD>(x, W1 + (size_t)e * HD * ID, ID, n0,
                 arow, sAhi, sAlo, sBhi, sBlo, acc);

    int lane = tid & 31, warp = tid >> 5;
    int warpM = (warp >> 2) * 64, warpN = (warp & 3) * 16;
    int qr = lane >> 2, qc = (lane & 3) * 2;
    const float* bb = b1 + (size_t)e * ID;
    #pragma unroll
    for (int mi = 0; mi < 4; mi++) {
        #pragma unroll
        for (int rr = 0; rr < 2; rr++) {
            int lrow = warpM + mi * 16 + rr * 8 + qr;
            int gr = rowTile + lrow;
            if (gr >= cnt) continue;
            float* hrow = d_h1 + (size_t)(base + gr) * ID + n0;
            #pragma unroll
            for (int ni = 0; ni < 2; ni++) {
                int n = warpN + ni * 8 + qc;
                float v0 = acc[mi][ni][rr * 2]     + bb[n0 + n];
                float v1 = acc[mi][ni][rr * 2 + 1] + bb[n0 + n + 1];
                hrow[n]     = 0.5f * v0 * (1.0f + erff(v0 * 0.70710678118654752f));
                hrow[n + 1] = 0.5f * v1 * (1.0f + erff(v1 * 0.70710678118654752f));
            }
        }
    }
}

// ===================== GEMM2: out += p * (h1 @ W2 + b2) =======================
__global__ void __launch_bounds__(512)
gemm2_hmma(const float* __restrict__ W2,
           const float* __restrict__ b2,
           float* __restrict__ out) {
    int e = blockIdx.z;
    int cnt = d_counts[e];
    int rowTile = blockIdx.y * 256;
    if (rowTile >= cnt) return;
    int base = d_offsets[e];
    int n0 = blockIdx.x * 64;

    __shared__ __nv_bfloat16 sAhi[256][32], sAlo[256][32];
    __shared__ __nv_bfloat16 sBhi[64][32],  sBlo[64][32];
    __shared__ int arow[256];
    __shared__ int stok[256];
    __shared__ float sprob[256];

    int tid = threadIdx.x;
    if (tid < 256) {
        int r = rowTile + tid;
        int rc = base + min(r, cnt - 1);
        arow[tid]  = rc;
        stok[tid]  = d_rowToken[rc];
        sprob[tid] = d_rowProb[rc];
    }
    __syncthreads();

    float acc[4][2][4] = {};
    mainloop<ID>(d_h1, W2 + (size_t)e * ID * HD, HD, n0,
                 arow, sAhi, sAlo, sBhi, sBlo, acc);

    int lane = tid & 31, warp = tid >> 5;
    int warpM = (warp >> 2) * 64, warpN = (warp & 3) * 16;
    int qr = lane >> 2, qc = (lane & 3) * 2;
    const float* bb = b2 + (size_t)e * HD;
    #pragma unroll
    for (int mi = 0; mi < 4; mi++) {
        #pragma unroll
        for (int rr = 0; rr < 2; rr++) {
            int lrow = warpM + mi * 16 + rr * 8 + qr;
            int gr = rowTile + lrow;
            if (gr >= cnt) continue;
            int tok = stok[lrow];
            float p = sprob[lrow];
            float* od = out + (size_t)tok * HD + n0;
            #pragma unroll
            for (int ni = 0; ni < 2; ni++) {
                int n = warpN + ni * 8 + qc;
                atomicAdd(&od[n],     p * (acc[mi][ni][rr * 2]     + bb[n0 + n]));
                atomicAdd(&od[n + 1], p * (acc[mi][ni][rr * 2 + 1] + bb[n0 + n + 1]));
            }
        }
    }
}

// ---------------- launch ----------------
extern "C" void kernel_launch(void* const* d_in, const int* in_sizes, int n_in,
                              void* d_out, int out_size) {
    const float* x     = (const float*)d_in[0];
    const float* gateW = (const float*)d_in[1];
    const float* gateB = (const float*)d_in[2];
    const float* W1    = (const float*)d_in[3];
    const float* b1    = (const float*)d_in[4];
    const float* W2    = (const float*)d_in[5];
    const float* b2    = (const float*)d_in[6];
    float* out = (float*)d_out;                    // [TOKENS*HD]
    float* out_gw = out + (size_t)TOKENS * HD;     // [TOKENS*NE]

    reset_counters_kernel<<<1, 32>>>();
    zero_out_kernel<<<(TOKENS * HD + 255) / 256, 256>>>(out, TOKENS * HD);
    gate_kernel<<<TOKENS, 224>>>(x, gateW, gateB, out_gw);
    offsets_kernel<<<1, 1>>>();
    scatter_kernel<<<(NA + 255) / 256, 256>>>();

    dim3 g1(ID / 64, NA / 256, NE);   // (48, 32, 7)
    gemm1_hmma<<<g1, 512>>>(x, W1, b1);

    dim3 g2(HD / 64, NA / 256, NE);   // (12, 32, 7)
    gemm2_hmma<<<g2, 512>>>(W2, b2, out);
}

// round 6
// speedup vs baseline: 1.9892x; 1.3656x over previous
#include <cuda_runtime.h>
#include <cuda_bf16.h>
#include <cstdint>
#include <math.h>

#define TOKENS 4096
#define HD 768
#define ID 3072
#define NE 7
#define NA (TOKENS * 2)   // 8192 assignments (top-2)

// ---------------- device scratch (static, no allocation) ----------------
__device__ int   d_counts[NE];
__device__ int   d_offsets[NE + 1];
__device__ int   d_cursor[NE];
__device__ int   d_tkExpert[NA];
__device__ float d_tkProb[NA];
__device__ int   d_rowToken[NA];
__device__ float d_rowProb[NA];
__device__ __align__(16) __nv_bfloat16 d_x_hi[(size_t)TOKENS * HD];   // 6 MB
__device__ __align__(16) __nv_bfloat16 d_x_lo[(size_t)TOKENS * HD];   // 6 MB
__device__ __align__(16) __nv_bfloat16 d_h1_hi[(size_t)NA * ID];      // 50 MB
__device__ __align__(16) __nv_bfloat16 d_h1_lo[(size_t)NA * ID];      // 50 MB

// ---------------- helpers ----------------
__device__ __forceinline__ void mma16816(float* c, const uint32_t* a,
                                         uint32_t b0, uint32_t b1) {
    asm volatile(
        "mma.sync.aligned.m16n8k16.row.col.f32.bf16.bf16.f32 "
        "{%0,%1,%2,%3}, {%4,%5,%6,%7}, {%8,%9}, {%0,%1,%2,%3};"
        : "+f"(c[0]), "+f"(c[1]), "+f"(c[2]), "+f"(c[3])
        : "r"(a[0]), "r"(a[1]), "r"(a[2]), "r"(a[3]), "r"(b0), "r"(b1));
}

__device__ __forceinline__ void ldsm4(uint32_t* r, const void* smem_ptr) {
    uint32_t addr = (uint32_t)__cvta_generic_to_shared(smem_ptr);
    asm volatile("ldmatrix.sync.aligned.m8n8.x4.shared.b16 {%0,%1,%2,%3}, [%4];"
                 : "=r"(r[0]), "=r"(r[1]), "=r"(r[2]), "=r"(r[3]) : "r"(addr));
}

__device__ __forceinline__ void split_bf(float v, __nv_bfloat16& h, __nv_bfloat16& l) {
    h = __float2bfloat16(v);
    l = __float2bfloat16(v - __bfloat162float(h));
}
__device__ __forceinline__ uint32_t pack_bf(__nv_bfloat16 a, __nv_bfloat16 b) {
    __nv_bfloat162 t; t.x = a; t.y = b;
    uint32_t r; memcpy(&r, &t, 4); return r;
}

// XOR swizzle on 8-element (16B) chunks within a 32-wide bf16 row.
__device__ __forceinline__ int swz(int row, int col) {
    return ((((col >> 3) ^ ((row >> 1) & 3)) & 3) << 3) | (col & 7);
}

// ---------------- small utility kernels ----------------
__global__ void reset_counters_kernel() {
    int i = threadIdx.x;
    if (i < NE) { d_counts[i] = 0; d_cursor[i] = 0; }
}

__global__ void zero_out_kernel(float* out, int n) {
    int i = blockIdx.x * blockDim.x + threadIdx.x;
    if (i < n) out[i] = 0.0f;
}

__global__ void split_x_kernel(const float* __restrict__ x) {
    int i = blockIdx.x * blockDim.x + threadIdx.x;
    if (i < TOKENS * HD) {
        __nv_bfloat16 h, l;
        split_bf(x[i], h, l);
        d_x_hi[i] = h; d_x_lo[i] = l;
    }
}

// ---------------- gate: logits, top-2 softmax, assignment build ----------------
__global__ void gate_kernel(const float* __restrict__ x,
                            const float* __restrict__ gW,
                            const float* __restrict__ gb,
                            float* __restrict__ out_gw) {
    int t = blockIdx.x;
    __shared__ float logits[NE];
    int w = threadIdx.x >> 5;
    int lane = threadIdx.x & 31;
    const float* xr = x + (size_t)t * HD;
    if (w < NE) {
        const float* wr = gW + (size_t)w * HD;
        float s = 0.0f;
        for (int h = lane; h < HD; h += 32) s += xr[h] * wr[h];
        #pragma unroll
        for (int o = 16; o; o >>= 1) s += __shfl_down_sync(0xffffffffu, s, o);
        if (lane == 0) logits[w] = s + gb[w];
    }
    __syncthreads();
    if (threadIdx.x == 0) {
        int i0 = 0;
        #pragma unroll
        for (int e = 1; e < NE; e++) if (logits[e] > logits[i0]) i0 = e;
        int i1 = -1;
        #pragma unroll
        for (int e = 0; e < NE; e++) {
            if (e == i0) continue;
            if (i1 < 0 || logits[e] > logits[i1]) i1 = e;
        }
        float v0 = logits[i0], v1 = logits[i1];
        float e1 = expf(v1 - v0);
        float inv = 1.0f / (1.0f + e1);
        float p0 = inv, p1 = e1 * inv;
        float* gw = out_gw + (size_t)t * NE;
        #pragma unroll
        for (int e = 0; e < NE; e++) gw[e] = 0.0f;
        gw[i0] = p0; gw[i1] = p1;
        d_tkExpert[t * 2 + 0] = i0; d_tkProb[t * 2 + 0] = p0;
        d_tkExpert[t * 2 + 1] = i1; d_tkProb[t * 2 + 1] = p1;
        atomicAdd(&d_counts[i0], 1);
        atomicAdd(&d_counts[i1], 1);
    }
}

__global__ void offsets_kernel() {
    int acc = 0;
    for (int e = 0; e < NE; e++) { d_offsets[e] = acc; acc += d_counts[e]; }
    d_offsets[NE] = acc;
}

__global__ void scatter_kernel() {
    int a = blockIdx.x * blockDim.x + threadIdx.x;
    if (a >= NA) return;
    int e = d_tkExpert[a];
    int pos = d_offsets[e] + atomicAdd(&d_cursor[e], 1);
    d_rowToken[pos] = a >> 1;
    d_rowProb[pos]  = d_tkProb[a];
}

// ---------------- HMMA mainloop (shared, unified) ----------------
// Block tile 256(M) x 64(N), k-tile 32.
//  - A comes pre-split as bf16 hi/lo global arrays (pure swizzled 16B copies).
//  - B is fp32 weight panel [KDIM][NDIM]; split to bf16 hi/lo in-kernel.
// 3-term compensation per k-chunk: Ahi*Bhi + Alo*Bhi + Ahi*Blo.
// 512 threads = 16 warps: 4 warps along M (64 rows) x 4 warps along N (16 cols).

template<int KDIM>
__device__ __forceinline__ void mainloop(
    const __nv_bfloat16* __restrict__ Ahi,
    const __nv_bfloat16* __restrict__ Alo,
    const float* __restrict__ W,     // expert weight [KDIM][NDIM] row-major
    int NDIM, int n0,
    const int* arow,                 // smem: 256 absolute row indices into A
    __nv_bfloat16 (*sAhi)[32], __nv_bfloat16 (*sAlo)[32],
    __nv_bfloat16 (*sBhi)[32], __nv_bfloat16 (*sBlo)[32],
    float acc[4][2][4])
{
    constexpr int KT = KDIM / 32;
    int tid = threadIdx.x;
    int lane = tid & 31, warp = tid >> 5;
    int warpM = (warp >> 2) * 64;
    int warpN = (warp & 3) * 16;
    int g = lane >> 3;           // ldmatrix group 0..3
    int lr = lane & 7;           // ldmatrix row-in-group

    // A copy assignment: two passes of (128 rows x 4 chunks)
    int car = tid >> 2, cac = tid & 3;                 // row 0..127, chunk 0..3
    const __nv_bfloat16* aHiSrc0 = Ahi + (size_t)arow[car]       * KDIM + cac * 8;
    const __nv_bfloat16* aLoSrc0 = Alo + (size_t)arow[car]       * KDIM + cac * 8;
    const __nv_bfloat16* aHiSrc1 = Ahi + (size_t)arow[car + 128] * KDIM + cac * 8;
    const __nv_bfloat16* aLoSrc1 = Alo + (size_t)arow[car + 128] * KDIM + cac * 8;
    int adst0 = swz(car, cac * 8);
    int adst1 = swz(car + 128, cac * 8);

    // B assignment: k-row 0..31, n group of 4
    int kr = tid & 31, ng = (tid >> 5) * 4;
    const float* bSrc = W + (size_t)kr * NDIM + n0 + ng;

    uint4 paHi0, paLo0, paHi1, paLo1; float4 pb;
    paHi0 = *(const uint4*)(aHiSrc0);
    paLo0 = *(const uint4*)(aLoSrc0);
    paHi1 = *(const uint4*)(aHiSrc1);
    paLo1 = *(const uint4*)(aLoSrc1);
    pb = *(const float4*)(bSrc);

    for (int kt = 0; kt < KT; kt++) {
        // ---- store prefetched tiles
        *(uint4*)&sAhi[car][adst0]       = paHi0;
        *(uint4*)&sAlo[car][adst0]       = paLo0;
        *(uint4*)&sAhi[car + 128][adst1] = paHi1;
        *(uint4*)&sAlo[car + 128][adst1] = paLo1;
        {
            float bv[4] = {pb.x, pb.y, pb.z, pb.w};
            #pragma unroll
            for (int i = 0; i < 4; i++) {
                __nv_bfloat16 h0, l0;
                split_bf(bv[i], h0, l0);
                int s = swz(ng + i, kr);
                sBhi[ng + i][s] = h0;
                sBlo[ng + i][s] = l0;
            }
        }
        __syncthreads();

        // ---- prefetch next k-tile
        if (kt + 1 < KT) {
            int ko = (kt + 1) * 32;
            paHi0 = *(const uint4*)(aHiSrc0 + ko);
            paLo0 = *(const uint4*)(aLoSrc0 + ko);
            paHi1 = *(const uint4*)(aHiSrc1 + ko);
            paLo1 = *(const uint4*)(aLoSrc1 + ko);
            pb = *(const float4*)(bSrc + (size_t)(kt + 1) * 32 * NDIM);
        }

        // ---- compute
        #pragma unroll
        for (int kk = 0; kk < 2; kk++) {
            uint32_t ah[4][4], al[4][4], bh[4], bl[4];
            // B: one x4 ldmatrix covers both n-halves and both k-chunks
            {
                int n = warpN + (g & 1) * 8 + lr;
                int ch = (kk * 2 + (g >> 1)) ^ ((n >> 1) & 3);
                ldsm4(bh, &sBhi[n][ch << 3]);
                ldsm4(bl, &sBlo[n][ch << 3]);
            }
            #pragma unroll
            for (int mi = 0; mi < 4; mi++) {
                int row = warpM + mi * 16 + (g & 1) * 8 + lr;
                int ch = (kk * 2 + (g >> 1)) ^ ((row >> 1) & 3);
                ldsm4(ah[mi], &sAhi[row][ch << 3]);
                ldsm4(al[mi], &sAlo[row][ch << 3]);
            }
            #pragma unroll
            for (int mi = 0; mi < 4; mi++) {
                mma16816(acc[mi][0], ah[mi], bh[0], bh[2]);
                mma16816(acc[mi][0], al[mi], bh[0], bh[2]);
                mma16816(acc[mi][0], ah[mi], bl[0], bl[2]);
                mma16816(acc[mi][1], ah[mi], bh[1], bh[3]);
                mma16816(acc[mi][1], al[mi], bh[1], bh[3]);
                mma16816(acc[mi][1], ah[mi], bl[1], bl[3]);
            }
        }
        __syncthreads();
    }
}

// ===================== GEMM1: h1 = gelu(x @ W1 + b1) ==========================
__global__ void __launch_bounds__(512)
gemm1_hmma(const float* __restrict__ W1,
           const float* __restrict__ b1) {
    int e = blockIdx.z;
    int cnt = d_counts[e];
    int rowTile = blockIdx.y * 256;
    if (rowTile >= cnt) return;
    int base = d_offsets[e];
    int n0 = blockIdx.x * 64;

    __shared__ __nv_bfloat16 sAhi[256][32], sAlo[256][32];
    __shared__ __nv_bfloat16 sBhi[64][32],  sBlo[64][32];
    __shared__ int arow[256];

    int tid = threadIdx.x;
    if (tid < 256) {
        int r = rowTile + tid;
        arow[tid] = d_rowToken[base + min(r, cnt - 1)];
    }
    __syncthreads();

    float acc[4][2][4] = {};
    mainloop<HD>(d_x_hi, d_x_lo, W1 + (size_t)e * HD * ID, ID, n0,
                 arow, sAhi, sAlo, sBhi, sBlo, acc);

    int lane = tid & 31, warp = tid >> 5;
    int warpM = (warp >> 2) * 64, warpN = (warp & 3) * 16;
    int qr = lane >> 2, qc = (lane & 3) * 2;
    const float* bb = b1 + (size_t)e * ID;
    #pragma unroll
    for (int mi = 0; mi < 4; mi++) {
        #pragma unroll
        for (int rr = 0; rr < 2; rr++) {
            int lrow = warpM + mi * 16 + rr * 8 + qr;
            int gr = rowTile + lrow;
            if (gr >= cnt) continue;
            size_t orow = (size_t)(base + gr) * ID + n0;
            #pragma unroll
            for (int ni = 0; ni < 2; ni++) {
                int n = warpN + ni * 8 + qc;
                float v0 = acc[mi][ni][rr * 2]     + bb[n0 + n];
                float v1 = acc[mi][ni][rr * 2 + 1] + bb[n0 + n + 1];
                float g0 = 0.5f * v0 * (1.0f + erff(v0 * 0.70710678118654752f));
                float g1 = 0.5f * v1 * (1.0f + erff(v1 * 0.70710678118654752f));
                __nv_bfloat16 h0, l0, h1v, l1v;
                split_bf(g0, h0, l0); split_bf(g1, h1v, l1v);
                *(uint32_t*)(d_h1_hi + orow + n) = pack_bf(h0, h1v);
                *(uint32_t*)(d_h1_lo + orow + n) = pack_bf(l0, l1v);
            }
        }
    }
}

// ===================== GEMM2: out += p * (h1 @ W2 + b2) =======================
__global__ void __launch_bounds__(512)
gemm2_hmma(const float* __restrict__ W2,
           const float* __restrict__ b2,
           float* __restrict__ out) {
    int e = blockIdx.z;
    int cnt = d_counts[e];
    int rowTile = blockIdx.y * 256;
    if (rowTile >= cnt) return;
    int base = d_offsets[e];
    int n0 = blockIdx.x * 64;

    __shared__ __nv_bfloat16 sAhi[256][32], sAlo[256][32];
    __shared__ __nv_bfloat16 sBhi[64][32],  sBlo[64][32];
    __shared__ int arow[256];
    __shared__ int stok[256];
    __shared__ float sprob[256];

    int tid = threadIdx.x;
    if (tid < 256) {
        int r = rowTile + tid;
        int rc = base + min(r, cnt - 1);
        arow[tid]  = rc;
        stok[tid]  = d_rowToken[rc];
        sprob[tid] = d_rowProb[rc];
    }
    __syncthreads();

    float acc[4][2][4] = {};
    mainloop<ID>(d_h1_hi, d_h1_lo, W2 + (size_t)e * ID * HD, HD, n0,
                 arow, sAhi, sAlo, sBhi, sBlo, acc);

    int lane = tid & 31, warp = tid >> 5;
    int warpM = (warp >> 2) * 64, warpN = (warp & 3) * 16;
    int qr = lane >> 2, qc = (lane & 3) * 2;
    const float* bb = b2 + (size_t)e * HD;
    #pragma unroll
    for (int mi = 0; mi < 4; mi++) {
        #pragma unroll
        for (int rr = 0; rr < 2; rr++) {
            int lrow = warpM + mi * 16 + rr * 8 + qr;
            int gr = rowTile + lrow;
            if (gr >= cnt) continue;
            int tok = stok[lrow];
            float p = sprob[lrow];
            float* od = out + (size_t)tok * HD + n0;
            #pragma unroll
            for (int ni = 0; ni < 2; ni++) {
                int n = warpN + ni * 8 + qc;
                atomicAdd(&od[n],     p * (acc[mi][ni][rr * 2]     + bb[n0 + n]));
                atomicAdd(&od[n + 1], p * (acc[mi][ni][rr * 2 + 1] + bb[n0 + n + 1]));
            }
        }
    }
}

// ---------------- launch ----------------
extern "C" void kernel_launch(void* const* d_in, const int* in_sizes, int n_in,
                              void* d_out, int out_size) {
    const float* x     = (const float*)d_in[0];
    const float* gateW = (const float*)d_in[1];
    const float* gateB = (const float*)d_in[2];
    const float* W1    = (const float*)d_in[3];
    const float* b1    = (const float*)d_in[4];
    const float* W2    = (const float*)d_in[5];
    const float* b2    = (const float*)d_in[6];
    float* out = (float*)d_out;                    // [TOKENS*HD]
    float* out_gw = out + (size_t)TOKENS * HD;     // [TOKENS*NE]

    reset_counters_kernel<<<1, 32>>>();
    zero_out_kernel<<<(TOKENS * HD + 255) / 256, 256>>>(out, TOKENS * HD);
    gate_kernel<<<TOKENS, 224>>>(x, gateW, gateB, out_gw);
    offsets_kernel<<<1, 1>>>();
    scatter_kernel<<<(NA + 255) / 256, 256>>>();
    split_x_kernel<<<(TOKENS * HD + 255) / 256, 256>>>(x);

    dim3 g1(ID / 64, NA / 256, NE);   // (48, 32, 7)
    gemm1_hmma<<<g1, 512>>>(W1, b1);

    dim3 g2(HD / 64, NA / 256, NE);   // (12, 32, 7)
    gemm2_hmma<<<g2, 512>>>(W2, b2, out);
}

// round 7
// speedup vs baseline: 2.7505x; 1.3827x over previous
#include <cuda_runtime.h>
#include <cuda_bf16.h>
#include <cstdint>
#include <math.h>

#define TOKENS 4096
#define HD 768
#define ID 3072
#define NE 7
#define NA (TOKENS * 2)   // 8192 assignments (top-2)

// ---------------- device scratch (static, no allocation) ----------------
__device__ int   d_counts[NE];
__device__ int   d_offsets[NE + 1];
__device__ int   d_cursor[NE];
__device__ int   d_tkExpert[NA];
__device__ float d_tkProb[NA];
__device__ int   d_rowToken[NA];
__device__ float d_rowProb[NA];
__device__ __align__(16) __nv_bfloat16 d_x_hi[(size_t)TOKENS * HD];     // 6 MB
__device__ __align__(16) __nv_bfloat16 d_x_lo[(size_t)TOKENS * HD];     // 6 MB
__device__ __align__(16) __nv_bfloat16 d_W1s_hi[(size_t)NE * HD * ID];  // 33 MB  [e][k][n]
__device__ __align__(16) __nv_bfloat16 d_W1s_lo[(size_t)NE * HD * ID];  // 33 MB
__device__ __align__(16) __nv_bfloat16 d_W2s_hi[(size_t)NE * ID * HD];  // 33 MB  [e][k][n]
__device__ __align__(16) __nv_bfloat16 d_W2s_lo[(size_t)NE * ID * HD];  // 33 MB
__device__ __align__(16) __nv_bfloat16 d_h1_hi[(size_t)NA * ID];        // 50 MB
__device__ __align__(16) __nv_bfloat16 d_h1_lo[(size_t)NA * ID];        // 50 MB

// ---------------- helpers ----------------
__device__ __forceinline__ void mma16816(float* c, const uint32_t* a,
                                         uint32_t b0, uint32_t b1) {
    asm volatile(
        "mma.sync.aligned.m16n8k16.row.col.f32.bf16.bf16.f32 "
        "{%0,%1,%2,%3}, {%4,%5,%6,%7}, {%8,%9}, {%0,%1,%2,%3};"
        : "+f"(c[0]), "+f"(c[1]), "+f"(c[2]), "+f"(c[3])
        : "r"(a[0]), "r"(a[1]), "r"(a[2]), "r"(a[3]), "r"(b0), "r"(b1));
}

__device__ __forceinline__ void ldsm4(uint32_t* r, uint32_t addr) {
    asm volatile("ldmatrix.sync.aligned.m8n8.x4.shared.b16 {%0,%1,%2,%3}, [%4];"
                 : "=r"(r[0]), "=r"(r[1]), "=r"(r[2]), "=r"(r[3]) : "r"(addr));
}
__device__ __forceinline__ void ldsm4t(uint32_t* r, uint32_t addr) {
    asm volatile("ldmatrix.sync.aligned.m8n8.x4.trans.shared.b16 {%0,%1,%2,%3}, [%4];"
                 : "=r"(r[0]), "=r"(r[1]), "=r"(r[2]), "=r"(r[3]) : "r"(addr));
}

__device__ __forceinline__ void cpasync16(uint32_t dst, const void* src) {
    asm volatile("cp.async.cg.shared.global [%0], [%1], 16;"
                 :: "r"(dst), "l"(src) : "memory");
}
__device__ __forceinline__ void cp_commit() {
    asm volatile("cp.async.commit_group;" ::: "memory");
}
__device__ __forceinline__ void cp_wait2() {
    asm volatile("cp.async.wait_group 2;" ::: "memory");
}

__device__ __forceinline__ void split_bf(float v, __nv_bfloat16& h, __nv_bfloat16& l) {
    h = __float2bfloat16(v);
    l = __float2bfloat16(v - __bfloat162float(h));
}
__device__ __forceinline__ uint32_t pack_bf(__nv_bfloat16 a, __nv_bfloat16 b) {
    __nv_bfloat162 t; t.x = a; t.y = b;
    uint32_t r; memcpy(&r, &t, 4); return r;
}

// ---------------- small utility kernels ----------------
__global__ void reset_counters_kernel() {
    int i = threadIdx.x;
    if (i < NE) { d_counts[i] = 0; d_cursor[i] = 0; }
}

__global__ void zero_out_kernel(float* out, int n) {
    int i = blockIdx.x * blockDim.x + threadIdx.x;
    if (i < n) out[i] = 0.0f;
}

__global__ void split_x_kernel(const float* __restrict__ x) {
    int i = blockIdx.x * blockDim.x + threadIdx.x;
    if (i < TOKENS * HD) {
        __nv_bfloat16 h, l;
        split_bf(x[i], h, l);
        d_x_hi[i] = h; d_x_lo[i] = l;
    }
}

// internally-referenced targets (NEVER pass __device__ arrays from host!)
__global__ void split_w1_kernel(const float* __restrict__ W1) {
    size_t i = (size_t)blockIdx.x * blockDim.x + threadIdx.x;
    if (i < (size_t)NE * HD * ID) {
        __nv_bfloat16 h, l;
        split_bf(W1[i], h, l);
        d_W1s_hi[i] = h; d_W1s_lo[i] = l;
    }
}
__global__ void split_w2_kernel(const float* __restrict__ W2) {
    size_t i = (size_t)blockIdx.x * blockDim.x + threadIdx.x;
    if (i < (size_t)NE * ID * HD) {
        __nv_bfloat16 h, l;
        split_bf(W2[i], h, l);
        d_W2s_hi[i] = h; d_W2s_lo[i] = l;
    }
}

// ---------------- gate: logits, top-2 softmax, assignment build ----------------
__global__ void gate_kernel(const float* __restrict__ x,
                            const float* __restrict__ gW,
                            const float* __restrict__ gb,
                            float* __restrict__ out_gw) {
    int t = blockIdx.x;
    __shared__ float logits[NE];
    int w = threadIdx.x >> 5;
    int lane = threadIdx.x & 31;
    const float* xr = x + (size_t)t * HD;
    if (w < NE) {
        const float* wr = gW + (size_t)w * HD;
        float s = 0.0f;
        for (int h = lane; h < HD; h += 32) s += xr[h] * wr[h];
        #pragma unroll
        for (int o = 16; o; o >>= 1) s += __shfl_down_sync(0xffffffffu, s, o);
        if (lane == 0) logits[w] = s + gb[w];
    }
    __syncthreads();
    if (threadIdx.x == 0) {
        int i0 = 0;
        #pragma unroll
        for (int e = 1; e < NE; e++) if (logits[e] > logits[i0]) i0 = e;
        int i1 = -1;
        #pragma unroll
        for (int e = 0; e < NE; e++) {
            if (e == i0) continue;
            if (i1 < 0 || logits[e] > logits[i1]) i1 = e;
        }
        float v0 = logits[i0], v1 = logits[i1];
        float e1 = expf(v1 - v0);
        float inv = 1.0f / (1.0f + e1);
        float p0 = inv, p1 = e1 * inv;
        float* gw = out_gw + (size_t)t * NE;
        #pragma unroll
        for (int e = 0; e < NE; e++) gw[e] = 0.0f;
        gw[i0] = p0; gw[i1] = p1;
        d_tkExpert[t * 2 + 0] = i0; d_tkProb[t * 2 + 0] = p0;
        d_tkExpert[t * 2 + 1] = i1; d_tkProb[t * 2 + 1] = p1;
        atomicAdd(&d_counts[i0], 1);
        atomicAdd(&d_counts[i1], 1);
    }
}

__global__ void offsets_kernel() {
    int acc = 0;
    for (int e = 0; e < NE; e++) { d_offsets[e] = acc; acc += d_counts[e]; }
    d_offsets[NE] = acc;
}

__global__ void scatter_kernel() {
    int a = blockIdx.x * blockDim.x + threadIdx.x;
    if (a >= NA) return;
    int e = d_tkExpert[a];
    int pos = d_offsets[e] + atomicAdd(&d_cursor[e], 1);
    d_rowToken[pos] = a >> 1;
    d_rowProb[pos]  = d_tkProb[a];
}

// ---------------- HMMA mainloop ----------------
// Tile 128(M) x 128(N), k-tile 32, 256 threads = 8 warps (2 M x 4 N),
// warp tile 64x32.  All operands pre-split bf16 hi/lo in global memory.
// cp.async 3-stage pipeline.  A smem [128][32] (rows 64B, chunk swz
// c^( (r>>1)&3 )); B smem [32][128] k-major (rows 256B, chunk swz c^(k&7)),
// fragments via ldmatrix.trans.  3-term compensation per k-chunk.
#define STG_A_HI 0u
#define STG_A_LO 8192u
#define STG_B_HI 16384u
#define STG_B_LO 24576u
#define STG_BYTES 32768u
#define DSMEM_BYTES (3 * 32768)

template<int KDIM>
__device__ __forceinline__ void mainloop(
    const __nv_bfloat16* __restrict__ Ahi,
    const __nv_bfloat16* __restrict__ Alo,
    const __nv_bfloat16* __restrict__ Bhi,   // [KDIM][NDIM]
    const __nv_bfloat16* __restrict__ Blo,
    int NDIM, int n0,
    const int* arow,                 // smem: 128 absolute row indices into A
    uint32_t sm,                     // u32 shared addr of dynamic smem
    float acc[4][4][4])
{
    constexpr int KT = KDIM / 32;
    int tid = threadIdx.x;
    int lane = tid & 31, warp = tid >> 5;
    int warpM = (warp >> 2) * 64;    // 2 M-warps
    int warpN = (warp & 3) * 32;     // 4 N-warps
    int g = lane >> 3;               // ldmatrix group 0..3
    int lr = lane & 7;               // row-in-group

    // ---- cp.async assignments: A 4 chunks (2 hi + 2 lo), B 4 chunks
    int acr = tid >> 1;              // A row 0..127
    int ac0 = (tid & 1) * 2;         // chunk 0 or 2
    const __nv_bfloat16* aHiSrc = Ahi + (size_t)arow[acr] * KDIM + ac0 * 8;
    const __nv_bfloat16* aLoSrc = Alo + (size_t)arow[acr] * KDIM + ac0 * 8;
    uint32_t aD0 = (uint32_t)(acr * 64 + (( ac0      ^ ((acr >> 1) & 3)) << 4));
    uint32_t aD1 = (uint32_t)(acr * 64 + (((ac0 + 1) ^ ((acr >> 1) & 3)) << 4));

    int bkr = tid >> 3;              // B k-row 0..31
    int bc0 = (tid & 7) * 2;         // chunk 0..14 even
    const __nv_bfloat16* bHiSrc = Bhi + (size_t)bkr * NDIM + n0 + bc0 * 8;
    const __nv_bfloat16* bLoSrc = Blo + (size_t)bkr * NDIM + n0 + bc0 * 8;
    uint32_t bD0 = (uint32_t)(bkr * 256 + (( bc0      ^ (bkr & 7)) << 4));
    uint32_t bD1 = (uint32_t)(bkr * 256 + (((bc0 + 1) ^ (bkr & 7)) << 4));

    auto load_stage = [&](int kt) {
        uint32_t sb = sm + (uint32_t)(kt % 3) * STG_BYTES;
        size_t ako = (size_t)kt * 32;
        size_t bko = (size_t)kt * 32 * NDIM;
        cpasync16(sb + STG_A_HI + aD0, aHiSrc + ako);
        cpasync16(sb + STG_A_HI + aD1, aHiSrc + ako + 8);
        cpasync16(sb + STG_A_LO + aD0, aLoSrc + ako);
        cpasync16(sb + STG_A_LO + aD1, aLoSrc + ako + 8);
        cpasync16(sb + STG_B_HI + bD0, bHiSrc + bko);
        cpasync16(sb + STG_B_HI + bD1, bHiSrc + bko + 8);
        cpasync16(sb + STG_B_LO + bD0, bLoSrc + bko);
        cpasync16(sb + STG_B_LO + bD1, bLoSrc + bko + 8);
    };

    auto compute_stage = [&](int s) {
        uint32_t sb = sm + (uint32_t)s * STG_BYTES;
        #pragma unroll
        for (int kk = 0; kk < 2; kk++) {
            uint32_t ah[4][4], al[4][4], bh[2][4], bl[2][4];
            #pragma unroll
            for (int mi = 0; mi < 4; mi++) {
                int row = warpM + mi * 16 + (g & 1) * 8 + lr;
                int ch = (kk * 2 + (g >> 1)) ^ ((row >> 1) & 3);
                ldsm4(ah[mi], sb + STG_A_HI + (uint32_t)(row * 64 + ch * 16));
                ldsm4(al[mi], sb + STG_A_LO + (uint32_t)(row * 64 + ch * 16));
            }
            #pragma unroll
            for (int nh = 0; nh < 2; nh++) {
                int k = kk * 16 + (g & 1) * 8 + lr;
                int n = warpN + nh * 16 + (g >> 1) * 8;
                int ch = (n >> 3) ^ (k & 7);
                ldsm4t(bh[nh], sb + STG_B_HI + (uint32_t)(k * 256 + ch * 16));
                ldsm4t(bl[nh], sb + STG_B_LO + (uint32_t)(k * 256 + ch * 16));
            }
            #pragma unroll
            for (int mi = 0; mi < 4; mi++) {
                #pragma unroll
                for (int j = 0; j < 4; j++) {
                    int nh = j >> 1, o = (j & 1) * 2;
                    mma16816(acc[mi][j], ah[mi], bh[nh][o], bh[nh][o + 1]);
                    mma16816(acc[mi][j], al[mi], bh[nh][o], bh[nh][o + 1]);
                    mma16816(acc[mi][j], ah[mi], bl[nh][o], bl[nh][o + 1]);
                }
            }
        }
    };

    load_stage(0); cp_commit();
    load_stage(1); cp_commit();
    load_stage(2); cp_commit();

    for (int kt = 0; kt < KT; kt++) {
        cp_wait2();
        __syncthreads();
        compute_stage(kt % 3);
        __syncthreads();
        if (kt + 3 < KT) load_stage(kt + 3);
        cp_commit();
    }
}

// ===================== GEMM1: h1 = gelu(x @ W1 + b1) ==========================
__global__ void __launch_bounds__(256, 2)
gemm1_hmma(const float* __restrict__ b1) {
    int e = blockIdx.z;
    int cnt = d_counts[e];
    int rowTile = blockIdx.y * 128;
    if (rowTile >= cnt) return;
    int base = d_offsets[e];
    int n0 = blockIdx.x * 128;

    extern __shared__ __align__(16) char dyn_raw[];
    uint32_t sm = (uint32_t)__cvta_generic_to_shared(dyn_raw);

    __shared__ int arow[128];
    int tid = threadIdx.x;
    if (tid < 128) {
        int r = rowTile + tid;
        arow[tid] = d_rowToken[base + min(r, cnt - 1)];
    }
    __syncthreads();

    float acc[4][4][4] = {};
    mainloop<HD>(d_x_hi, d_x_lo,
                 d_W1s_hi + (size_t)e * HD * ID,
                 d_W1s_lo + (size_t)e * HD * ID,
                 ID, n0, arow, sm, acc);

    int lane = tid & 31, warp = tid >> 5;
    int warpM = (warp >> 2) * 64, warpN = (warp & 3) * 32;
    int qr = lane >> 2, qc = (lane & 3) * 2;
    const float* bb = b1 + (size_t)e * ID;
    #pragma unroll
    for (int mi = 0; mi < 4; mi++) {
        #pragma unroll
        for (int rr = 0; rr < 2; rr++) {
            int lrow = warpM + mi * 16 + rr * 8 + qr;
            int gr = rowTile + lrow;
            if (gr >= cnt) continue;
            size_t orow = (size_t)(base + gr) * ID + n0;
            #pragma unroll
            for (int j = 0; j < 4; j++) {
                int n = warpN + j * 8 + qc;
                float v0 = acc[mi][j][rr * 2]     + bb[n0 + n];
                float v1 = acc[mi][j][rr * 2 + 1] + bb[n0 + n + 1];
                float g0 = 0.5f * v0 * (1.0f + erff(v0 * 0.70710678118654752f));
                float g1 = 0.5f * v1 * (1.0f + erff(v1 * 0.70710678118654752f));
                __nv_bfloat16 h0, l0, h1v, l1v;
                split_bf(g0, h0, l0); split_bf(g1, h1v, l1v);
                *(uint32_t*)(d_h1_hi + orow + n) = pack_bf(h0, h1v);
                *(uint32_t*)(d_h1_lo + orow + n) = pack_bf(l0, l1v);
            }
        }
    }
}

// ===================== GEMM2: out += p * (h1 @ W2 + b2) =======================
__global__ void __launch_bounds__(256, 2)
gemm2_hmma(const float* __restrict__ b2, float* __restrict__ out) {
    int e = blockIdx.z;
    int cnt = d_counts[e];
    int rowTile = blockIdx.y * 128;
    if (rowTile >= cnt) return;
    int base = d_offsets[e];
    int n0 = blockIdx.x * 128;

    extern __shared__ __align__(16) char dyn_raw[];
    uint32_t sm = (uint32_t)__cvta_generic_to_shared(dyn_raw);

    __shared__ int arow[128];
    __shared__ int stok[128];
    __shared__ float sprob[128];
    int tid = threadIdx.x;
    if (tid < 128) {
        int r = rowTile + tid;
        int rc = base + min(r, cnt - 1);
        arow[tid]  = rc;
        stok[tid]  = d_rowToken[rc];
        sprob[tid] = d_rowProb[rc];
    }
    __syncthreads();

    float acc[4][4][4] = {};
    mainloop<ID>(d_h1_hi, d_h1_lo,
                 d_W2s_hi + (size_t)e * ID * HD,
                 d_W2s_lo + (size_t)e * ID * HD,
                 HD, n0, arow, sm, acc);

    int lane = tid & 31, warp = tid >> 5;
    int warpM = (warp >> 2) * 64, warpN = (warp & 3) * 32;
    int qr = lane >> 2, qc = (lane & 3) * 2;
    const float* bb = b2 + (size_t)e * HD;
    #pragma unroll
    for (int mi = 0; mi < 4; mi++) {
        #pragma unroll
        for (int rr = 0; rr < 2; rr++) {
            int lrow = warpM + mi * 16 + rr * 8 + qr;
            int gr = rowTile + lrow;
            if (gr >= cnt) continue;
            int tok = stok[lrow];
            float p = sprob[lrow];
            float* od = out + (size_t)tok * HD + n0;
            #pragma unroll
            for (int j = 0; j < 4; j++) {
                int n = warpN + j * 8 + qc;
                atomicAdd(&od[n],     p * (acc[mi][j][rr * 2]     + bb[n0 + n]));
                atomicAdd(&od[n + 1], p * (acc[mi][j][rr * 2 + 1] + bb[n0 + n + 1]));
            }
        }
    }
}

// ---------------- launch ----------------
extern "C" void kernel_launch(void* const* d_in, const int* in_sizes, int n_in,
                              void* d_out, int out_size) {
    const float* x     = (const float*)d_in[0];
    const float* gateW = (const float*)d_in[1];
    const float* gateB = (const float*)d_in[2];
    const float* W1    = (const float*)d_in[3];
    const float* b1    = (const float*)d_in[4];
    const float* W2    = (const float*)d_in[5];
    const float* b2    = (const float*)d_in[6];
    float* out = (float*)d_out;                    // [TOKENS*HD]
    float* out_gw = out + (size_t)TOKENS * HD;     // [TOKENS*NE]

    cudaFuncSetAttribute(gemm1_hmma, cudaFuncAttributeMaxDynamicSharedMemorySize, DSMEM_BYTES);
    cudaFuncSetAttribute(gemm2_hmma, cudaFuncAttributeMaxDynamicSharedMemorySize, DSMEM_BYTES);

    reset_counters_kernel<<<1, 32>>>();
    zero_out_kernel<<<(TOKENS * HD + 255) / 256, 256>>>(out, TOKENS * HD);
    gate_kernel<<<TOKENS, 224>>>(x, gateW, gateB, out_gw);
    offsets_kernel<<<1, 1>>>();
    scatter_kernel<<<(NA + 255) / 256, 256>>>();
    split_x_kernel<<<(TOKENS * HD + 255) / 256, 256>>>(x);
    {
        size_t nw = (size_t)NE * HD * ID;
        int blocks = (int)((nw + 255) / 256);
        split_w1_kernel<<<blocks, 256>>>(W1);
        split_w2_kernel<<<blocks, 256>>>(W2);
    }

    dim3 g1(ID / 128, NA / 128, NE);   // (24, 64, 7)
    gemm1_hmma<<<g1, 256, DSMEM_BYTES>>>(b1);

    dim3 g2(HD / 128, NA / 128, NE);   // (6, 64, 7)
    gemm2_hmma<<<g2, 256, DSMEM_BYTES>>>(b2, out);
}

// round 8
// speedup vs baseline: 3.3274x; 1.2098x over previous
#include <cuda_runtime.h>
#include <cuda_fp16.h>
#include <cstdint>
#include <math.h>

#define TOKENS 4096
#define HD 768
#define ID 3072
#define NE 7
#define NA (TOKENS * 2)   // 8192 assignments (top-2)

// ---------------- device scratch (static, no allocation) ----------------
__device__ int   d_counts[NE];
__device__ int   d_offsets[NE + 1];
__device__ int   d_cursor[NE];
__device__ int   d_tkExpert[NA];
__device__ float d_tkProb[NA];
__device__ int   d_rowToken[NA];
__device__ float d_rowProb[NA];
__device__ __align__(16) __half d_x_hi[(size_t)TOKENS * HD];     // 6 MB
__device__ __align__(16) __half d_x_lo[(size_t)TOKENS * HD];     // 6 MB
__device__ __align__(16) __half d_W1s_hi[(size_t)NE * HD * ID];  // 33 MB  [e][k][n]
__device__ __align__(16) __half d_W1s_lo[(size_t)NE * HD * ID];  // 33 MB
__device__ __align__(16) __half d_W2s_hi[(size_t)NE * ID * HD];  // 33 MB  [e][k][n]
__device__ __align__(16) __half d_W2s_lo[(size_t)NE * ID * HD];  // 33 MB
__device__ __align__(16) __half d_h1_hi[(size_t)NA * ID];        // 50 MB
__device__ __align__(16) __half d_h1_lo[(size_t)NA * ID];        // 50 MB

// ---------------- helpers ----------------
__device__ __forceinline__ void mma16816(float* c, const uint32_t* a,
                                         uint32_t b0, uint32_t b1) {
    asm volatile(
        "mma.sync.aligned.m16n8k16.row.col.f32.f16.f16.f32 "
        "{%0,%1,%2,%3}, {%4,%5,%6,%7}, {%8,%9}, {%0,%1,%2,%3};"
        : "+f"(c[0]), "+f"(c[1]), "+f"(c[2]), "+f"(c[3])
        : "r"(a[0]), "r"(a[1]), "r"(a[2]), "r"(a[3]), "r"(b0), "r"(b1));
}

__device__ __forceinline__ void ldsm4(uint32_t* r, uint32_t addr) {
    asm volatile("ldmatrix.sync.aligned.m8n8.x4.shared.b16 {%0,%1,%2,%3}, [%4];"
                 : "=r"(r[0]), "=r"(r[1]), "=r"(r[2]), "=r"(r[3]) : "r"(addr));
}
__device__ __forceinline__ void ldsm4t(uint32_t* r, uint32_t addr) {
    asm volatile("ldmatrix.sync.aligned.m8n8.x4.trans.shared.b16 {%0,%1,%2,%3}, [%4];"
                 : "=r"(r[0]), "=r"(r[1]), "=r"(r[2]), "=r"(r[3]) : "r"(addr));
}

__device__ __forceinline__ void cpasync16(uint32_t dst, const void* src) {
    asm volatile("cp.async.cg.shared.global [%0], [%1], 16;"
                 :: "r"(dst), "l"(src) : "memory");
}
__device__ __forceinline__ void cp_commit() {
    asm volatile("cp.async.commit_group;" ::: "memory");
}
__device__ __forceinline__ void cp_wait2() {
    asm volatile("cp.async.wait_group 2;" ::: "memory");
}

__device__ __forceinline__ void split_h(float v, __half& h, __half& l) {
    h = __float2half(v);
    l = __float2half(v - __half2float(h));
}
__device__ __forceinline__ uint32_t pack_h(__half a, __half b) {
    __half2 t; t.x = a; t.y = b;
    uint32_t r; memcpy(&r, &t, 4); return r;
}

// ---------------- small utility kernels ----------------
__global__ void reset_counters_kernel() {
    int i = threadIdx.x;
    if (i < NE) { d_counts[i] = 0; d_cursor[i] = 0; }
}

__global__ void zero_out_kernel(float* out, int n) {
    int i = blockIdx.x * blockDim.x + threadIdx.x;
    if (i < n) out[i] = 0.0f;
}

__global__ void split_x_kernel(const float* __restrict__ x) {
    int i = blockIdx.x * blockDim.x + threadIdx.x;
    if (i < TOKENS * HD) {
        __half h, l;
        split_h(x[i], h, l);
        d_x_hi[i] = h; d_x_lo[i] = l;
    }
}

// internally-referenced targets (NEVER pass __device__ arrays from host!)
__global__ void split_w1_kernel(const float* __restrict__ W1) {
    size_t i = (size_t)blockIdx.x * blockDim.x + threadIdx.x;
    if (i < (size_t)NE * HD * ID) {
        __half h, l;
        split_h(W1[i], h, l);
        d_W1s_hi[i] = h; d_W1s_lo[i] = l;
    }
}
__global__ void split_w2_kernel(const float* __restrict__ W2) {
    size_t i = (size_t)blockIdx.x * blockDim.x + threadIdx.x;
    if (i < (size_t)NE * ID * HD) {
        __half h, l;
        split_h(W2[i], h, l);
        d_W2s_hi[i] = h; d_W2s_lo[i] = l;
    }
}

// ---------------- gate: logits, top-2 softmax, assignment build ----------------
__global__ void gate_kernel(const float* __restrict__ x,
                            const float* __restrict__ gW,
                            const float* __restrict__ gb,
                            float* __restrict__ out_gw) {
    int t = blockIdx.x;
    __shared__ float logits[NE];
    int w = threadIdx.x >> 5;
    int lane = threadIdx.x & 31;
    const float* xr = x + (size_t)t * HD;
    if (w < NE) {
        const float* wr = gW + (size_t)w * HD;
        float s = 0.0f;
        for (int h = lane; h < HD; h += 32) s += xr[h] * wr[h];
        #pragma unroll
        for (int o = 16; o; o >>= 1) s += __shfl_down_sync(0xffffffffu, s, o);
        if (lane == 0) logits[w] = s + gb[w];
    }
    __syncthreads();
    if (threadIdx.x == 0) {
        int i0 = 0;
        #pragma unroll
        for (int e = 1; e < NE; e++) if (logits[e] > logits[i0]) i0 = e;
        int i1 = -1;
        #pragma unroll
        for (int e = 0; e < NE; e++) {
            if (e == i0) continue;
            if (i1 < 0 || logits[e] > logits[i1]) i1 = e;
        }
        float v0 = logits[i0], v1 = logits[i1];
        float e1 = expf(v1 - v0);
        float inv = 1.0f / (1.0f + e1);
        float p0 = inv, p1 = e1 * inv;
        float* gw = out_gw + (size_t)t * NE;
        #pragma unroll
        for (int e = 0; e < NE; e++) gw[e] = 0.0f;
        gw[i0] = p0; gw[i1] = p1;
        d_tkExpert[t * 2 + 0] = i0; d_tkProb[t * 2 + 0] = p0;
        d_tkExpert[t * 2 + 1] = i1; d_tkProb[t * 2 + 1] = p1;
        atomicAdd(&d_counts[i0], 1);
        atomicAdd(&d_counts[i1], 1);
    }
}

__global__ void offsets_kernel() {
    int acc = 0;
    for (int e = 0; e < NE; e++) { d_offsets[e] = acc; acc += d_counts[e]; }
    d_offsets[NE] = acc;
}

__global__ void scatter_kernel() {
    int a = blockIdx.x * blockDim.x + threadIdx.x;
    if (a >= NA) return;
    int e = d_tkExpert[a];
    int pos = d_offsets[e] + atomicAdd(&d_cursor[e], 1);
    d_rowToken[pos] = a >> 1;
    d_rowProb[pos]  = d_tkProb[a];
}

// ---------------- HMMA mainloop ----------------
// Tile 128(M) x 128(N), k-tile 32, 256 threads = 8 warps (2 M x 4 N),
// warp tile 64x32.  All operands pre-split fp16 hi/lo in global memory.
// cp.async 3-stage pipeline.  A smem [128][32] (rows 64B, chunk swz
// c^( (r>>1)&3 )); B smem [32][128] k-major (rows 256B, chunk swz c^(k&7)),
// fragments via ldmatrix.trans.
// 2-term compensation per k-chunk:  (Ahi + Alo) * Bhi   (A·Blo dropped, ~2^-12)
#define STG_A_HI 0u
#define STG_A_LO 8192u
#define STG_B_HI 16384u
#define STG_B_LO 24576u
#define STG_BYTES 32768u
#define DSMEM_BYTES (3 * 32768)

template<int KDIM>
__device__ __forceinline__ void mainloop(
    const __half* __restrict__ Ahi,
    const __half* __restrict__ Alo,
    const __half* __restrict__ Bhi,   // [KDIM][NDIM]
    const __half* __restrict__ Blo,
    int NDIM, int n0,
    const int* arow,                 // smem: 128 absolute row indices into A
    uint32_t sm,                     // u32 shared addr of dynamic smem
    float acc[4][4][4])
{
    constexpr int KT = KDIM / 32;
    int tid = threadIdx.x;
    int lane = tid & 31, warp = tid >> 5;
    int warpM = (warp >> 2) * 64;    // 2 M-warps
    int warpN = (warp & 3) * 32;     // 4 N-warps
    int g = lane >> 3;               // ldmatrix group 0..3
    int lr = lane & 7;               // row-in-group

    // ---- cp.async assignments: A 4 chunks (2 hi + 2 lo), B 4 chunks
    int acr = tid >> 1;              // A row 0..127
    int ac0 = (tid & 1) * 2;         // chunk 0 or 2
    const __half* aHiSrc = Ahi + (size_t)arow[acr] * KDIM + ac0 * 8;
    const __half* aLoSrc = Alo + (size_t)arow[acr] * KDIM + ac0 * 8;
    uint32_t aD0 = (uint32_t)(acr * 64 + (( ac0      ^ ((acr >> 1) & 3)) << 4));
    uint32_t aD1 = (uint32_t)(acr * 64 + (((ac0 + 1) ^ ((acr >> 1) & 3)) << 4));

    int bkr = tid >> 3;              // B k-row 0..31
    int bc0 = (tid & 7) * 2;         // chunk 0..14 even
    const __half* bHiSrc = Bhi + (size_t)bkr * NDIM + n0 + bc0 * 8;
    const __half* bLoSrc = Blo + (size_t)bkr * NDIM + n0 + bc0 * 8;
    uint32_t bD0 = (uint32_t)(bkr * 256 + (( bc0      ^ (bkr & 7)) << 4));
    uint32_t bD1 = (uint32_t)(bkr * 256 + (((bc0 + 1) ^ (bkr & 7)) << 4));

    auto load_stage = [&](int kt) {
        uint32_t sb = sm + (uint32_t)(kt % 3) * STG_BYTES;
        size_t ako = (size_t)kt * 32;
        size_t bko = (size_t)kt * 32 * NDIM;
        cpasync16(sb + STG_A_HI + aD0, aHiSrc + ako);
        cpasync16(sb + STG_A_HI + aD1, aHiSrc + ako + 8);
        cpasync16(sb + STG_A_LO + aD0, aLoSrc + ako);
        cpasync16(sb + STG_A_LO + aD1, aLoSrc + ako + 8);
        cpasync16(sb + STG_B_HI + bD0, bHiSrc + bko);
        cpasync16(sb + STG_B_HI + bD1, bHiSrc + bko + 8);
        cpasync16(sb + STG_B_LO + bD0, bLoSrc + bko);
        cpasync16(sb + STG_B_LO + bD1, bLoSrc + bko + 8);
    };

    auto compute_stage = [&](int s) {
        uint32_t sb = sm + (uint32_t)s * STG_BYTES;
        #pragma unroll
        for (int kk = 0; kk < 2; kk++) {
            uint32_t ah[4][4], al[4][4], bh[2][4];
            #pragma unroll
            for (int mi = 0; mi < 4; mi++) {
                int row = warpM + mi * 16 + (g & 1) * 8 + lr;
                int ch = (kk * 2 + (g >> 1)) ^ ((row >> 1) & 3);
                ldsm4(ah[mi], sb + STG_A_HI + (uint32_t)(row * 64 + ch * 16));
                ldsm4(al[mi], sb + STG_A_LO + (uint32_t)(row * 64 + ch * 16));
            }
            #pragma unroll
            for (int nh = 0; nh < 2; nh++) {
                int k = kk * 16 + (g & 1) * 8 + lr;
                int n = warpN + nh * 16 + (g >> 1) * 8;
                int ch = (n >> 3) ^ (k & 7);
                ldsm4t(bh[nh], sb + STG_B_HI + (uint32_t)(k * 256 + ch * 16));
            }
            #pragma unroll
            for (int mi = 0; mi < 4; mi++) {
                #pragma unroll
                for (int j = 0; j < 4; j++) {
                    int nh = j >> 1, o = (j & 1) * 2;
                    mma16816(acc[mi][j], ah[mi], bh[nh][o], bh[nh][o + 1]);
                    mma16816(acc[mi][j], al[mi], bh[nh][o], bh[nh][o + 1]);
                }
            }
        }
    };

    load_stage(0); cp_commit();
    load_stage(1); cp_commit();
    load_stage(2); cp_commit();

    for (int kt = 0; kt < KT; kt++) {
        cp_wait2();
        __syncthreads();
        compute_stage(kt % 3);
        __syncthreads();
        if (kt + 3 < KT) load_stage(kt + 3);
        cp_commit();
    }
}

// ===================== GEMM1: h1 = gelu(x @ W1 + b1) ==========================
__global__ void __launch_bounds__(256, 2)
gemm1_hmma(const float* __restrict__ b1) {
    int e = blockIdx.z;
    int cnt = d_counts[e];
    int rowTile = blockIdx.y * 128;
    if (rowTile >= cnt) return;
    int base = d_offsets[e];
    int n0 = blockIdx.x * 128;

    extern __shared__ __align__(16) char dyn_raw[];
    uint32_t sm = (uint32_t)__cvta_generic_to_shared(dyn_raw);

    __shared__ int arow[128];
    int tid = threadIdx.x;
    if (tid < 128) {
        int r = rowTile + tid;
        arow[tid] = d_rowToken[base + min(r, cnt - 1)];
    }
    __syncthreads();

    float acc[4][4][4] = {};
    mainloop<HD>(d_x_hi, d_x_lo,
                 d_W1s_hi + (size_t)e * HD * ID,
                 d_W1s_lo + (size_t)e * HD * ID,
                 ID, n0, arow, sm, acc);

    int lane = tid & 31, warp = tid >> 5;
    int warpM = (warp >> 2) * 64, warpN = (warp & 3) * 32;
    int qr = lane >> 2, qc = (lane & 3) * 2;
    const float* bb = b1 + (size_t)e * ID;
    #pragma unroll
    for (int mi = 0; mi < 4; mi++) {
        #pragma unroll
        for (int rr = 0; rr < 2; rr++) {
            int lrow = warpM + mi * 16 + rr * 8 + qr;
            int gr = rowTile + lrow;
            if (gr >= cnt) continue;
            size_t orow = (size_t)(base + gr) * ID + n0;
            #pragma unroll
            for (int j = 0; j < 4; j++) {
                int n = warpN + j * 8 + qc;
                float v0 = acc[mi][j][rr * 2]     + bb[n0 + n];
                float v1 = acc[mi][j][rr * 2 + 1] + bb[n0 + n + 1];
                float g0 = 0.5f * v0 * (1.0f + erff(v0 * 0.70710678118654752f));
                float g1 = 0.5f * v1 * (1.0f + erff(v1 * 0.70710678118654752f));
                __half h0, l0, h1v, l1v;
                split_h(g0, h0, l0); split_h(g1, h1v, l1v);
                *(uint32_t*)(d_h1_hi + orow + n) = pack_h(h0, h1v);
                *(uint32_t*)(d_h1_lo + orow + n) = pack_h(l0, l1v);
            }
        }
    }
}

// ===================== GEMM2: out += p * (h1 @ W2 + b2) =======================
__global__ void __launch_bounds__(256, 2)
gemm2_hmma(const float* __restrict__ b2, float* __restrict__ out) {
    int e = blockIdx.z;
    int cnt = d_counts[e];
    int rowTile = blockIdx.y * 128;
    if (rowTile >= cnt) return;
    int base = d_offsets[e];
    int n0 = blockIdx.x * 128;

    extern __shared__ __align__(16) char dyn_raw[];
    uint32_t sm = (uint32_t)__cvta_generic_to_shared(dyn_raw);

    __shared__ int arow[128];
    __shared__ int stok[128];
    __shared__ float sprob[128];
    int tid = threadIdx.x;
    if (tid < 128) {
        int r = rowTile + tid;
        int rc = base + min(r, cnt - 1);
        arow[tid]  = rc;
        stok[tid]  = d_rowToken[rc];
        sprob[tid] = d_rowProb[rc];
    }
    __syncthreads();

    float acc[4][4][4] = {};
    mainloop<ID>(d_h1_hi, d_h1_lo,
                 d_W2s_hi + (size_t)e * ID * HD,
                 d_W2s_lo + (size_t)e * ID * HD,
                 HD, n0, arow, sm, acc);

    int lane = tid & 31, warp = tid >> 5;
    int warpM = (warp >> 2) * 64, warpN = (warp & 3) * 32;
    int qr = lane >> 2, qc = (lane & 3) * 2;
    const float* bb = b2 + (size_t)e * HD;
    #pragma unroll
    for (int mi = 0; mi < 4; mi++) {
        #pragma unroll
        for (int rr = 0; rr < 2; rr++) {
            int lrow = warpM + mi * 16 + rr * 8 + qr;
            int gr = rowTile + lrow;
            if (gr >= cnt) continue;
            int tok = stok[lrow];
            float p = sprob[lrow];
            float* od = out + (size_t)tok * HD + n0;
            #pragma unroll
            for (int j = 0; j < 4; j++) {
                int n = warpN + j * 8 + qc;
                atomicAdd(&od[n],     p * (acc[mi][j][rr * 2]     + bb[n0 + n]));
                atomicAdd(&od[n + 1], p * (acc[mi][j][rr * 2 + 1] + bb[n0 + n + 1]));
            }
        }
    }
}

// ---------------- launch ----------------
extern "C" void kernel_launch(void* const* d_in, const int* in_sizes, int n_in,
                              void* d_out, int out_size) {
    const float* x     = (const float*)d_in[0];
    const float* gateW = (const float*)d_in[1];
    const float* gateB = (const float*)d_in[2];
    const float* W1    = (const float*)d_in[3];
    const float* b1    = (const float*)d_in[4];
    const float* W2    = (const float*)d_in[5];
    const float* b2    = (const float*)d_in[6];
    float* out = (float*)d_out;                    // [TOKENS*HD]
    float* out_gw = out + (size_t)TOKENS * HD;     // [TOKENS*NE]

    cudaFuncSetAttribute(gemm1_hmma, cudaFuncAttributeMaxDynamicSharedMemorySize, DSMEM_BYTES);
    cudaFuncSetAttribute(gemm2_hmma, cudaFuncAttributeMaxDynamicSharedMemorySize, DSMEM_BYTES);

    reset_counters_kernel<<<1, 32>>>();
    zero_out_kernel<<<(TOKENS * HD + 255) / 256, 256>>>(out, TOKENS * HD);
    gate_kernel<<<TOKENS, 224>>>(x, gateW, gateB, out_gw);
    offsets_kernel<<<1, 1>>>();
    scatter_kernel<<<(NA + 255) / 256, 256>>>();
    split_x_kernel<<<(TOKENS * HD + 255) / 256, 256>>>(x);
    {
        size_t nw = (size_t)NE * HD * ID;
        int blocks = (int)((nw + 255) / 256);
        split_w1_kernel<<<blocks, 256>>>(W1);
        split_w2_kernel<<<blocks, 256>>>(W2);
    }

    dim3 g1(ID / 128, NA / 128, NE);   // (24, 64, 7)
    gemm1_hmma<<<g1, 256, DSMEM_BYTES>>>(b1);

    dim3 g2(HD / 128, NA / 128, NE);   // (6, 64, 7)
    gemm2_hmma<<<g2, 256, DSMEM_BYTES>>>(b2, out);
}

// round 9
// speedup vs baseline: 3.6873x; 1.1082x over previous
#include <cuda_runtime.h>
#include <cuda_fp16.h>
#include <cstdint>
#include <math.h>

#define TOKENS 4096
#define HD 768
#define ID 3072
#define NE 7
#define NA (TOKENS * 2)   // 8192 assignments (top-2)

// ---------------- device scratch (static, no allocation) ----------------
__device__ int   d_counts[NE];
__device__ int   d_offsets[NE + 1];
__device__ int   d_cursor[NE];
__device__ int   d_tkExpert[NA];
__device__ float d_tkProb[NA];
__device__ int   d_rowToken[NA];
__device__ float d_rowProb[NA];
__device__ __align__(16) __half d_x_hi[(size_t)TOKENS * HD];     // 6 MB
__device__ __align__(16) __half d_x_lo[(size_t)TOKENS * HD];     // 6 MB
__device__ __align__(16) __half d_W1s_hi[(size_t)NE * HD * ID];  // 33 MB  [e][k][n]
__device__ __align__(16) __half d_W2s_hi[(size_t)NE * ID * HD];  // 33 MB  [e][k][n]
__device__ __align__(16) __half d_h1_hi[(size_t)NA * ID];        // 50 MB
__device__ __align__(16) __half d_h1_lo[(size_t)NA * ID];        // 50 MB

// ---------------- helpers ----------------
__device__ __forceinline__ void mma16816(float* c, const uint32_t* a,
                                         uint32_t b0, uint32_t b1) {
    asm volatile(
        "mma.sync.aligned.m16n8k16.row.col.f32.f16.f16.f32 "
        "{%0,%1,%2,%3}, {%4,%5,%6,%7}, {%8,%9}, {%0,%1,%2,%3};"
        : "+f"(c[0]), "+f"(c[1]), "+f"(c[2]), "+f"(c[3])
        : "r"(a[0]), "r"(a[1]), "r"(a[2]), "r"(a[3]), "r"(b0), "r"(b1));
}

__device__ __forceinline__ void ldsm4(uint32_t* r, uint32_t addr) {
    asm volatile("ldmatrix.sync.aligned.m8n8.x4.shared.b16 {%0,%1,%2,%3}, [%4];"
                 : "=r"(r[0]), "=r"(r[1]), "=r"(r[2]), "=r"(r[3]) : "r"(addr));
}
__device__ __forceinline__ void ldsm4t(uint32_t* r, uint32_t addr) {
    asm volatile("ldmatrix.sync.aligned.m8n8.x4.trans.shared.b16 {%0,%1,%2,%3}, [%4];"
                 : "=r"(r[0]), "=r"(r[1]), "=r"(r[2]), "=r"(r[3]) : "r"(addr));
}

__device__ __forceinline__ void cpasync16(uint32_t dst, const void* src) {
    asm volatile("cp.async.cg.shared.global [%0], [%1], 16;"
                 :: "r"(dst), "l"(src) : "memory");
}
__device__ __forceinline__ void cp_commit() {
    asm volatile("cp.async.commit_group;" ::: "memory");
}
__device__ __forceinline__ void cp_wait2() {
    asm volatile("cp.async.wait_group 2;" ::: "memory");
}

__device__ __forceinline__ void split_h(float v, __half& h, __half& l) {
    h = __float2half(v);
    l = __float2half(v - __half2float(h));
}
__device__ __forceinline__ uint32_t pack_h(__half a, __half b) {
    __half2 t; t.x = a; t.y = b;
    uint32_t r; memcpy(&r, &t, 4); return r;
}

// ---------------- small utility kernels ----------------
__global__ void reset_counters_kernel() {
    int i = threadIdx.x;
    if (i < NE) { d_counts[i] = 0; d_cursor[i] = 0; }
}

__global__ void zero_out_kernel(float* out, int n) {
    int i = blockIdx.x * blockDim.x + threadIdx.x;
    if (i < n) out[i] = 0.0f;
}

__global__ void split_x_kernel(const float* __restrict__ x) {
    int i = blockIdx.x * blockDim.x + threadIdx.x;
    if (i < TOKENS * HD) {
        __half h, l;
        split_h(x[i], h, l);
        d_x_hi[i] = h; d_x_lo[i] = l;
    }
}

// hi-only conversion (B's lo term is never used by the 2-term scheme)
__global__ void conv_w1_kernel(const float* __restrict__ W1) {
    size_t i = (size_t)blockIdx.x * blockDim.x + threadIdx.x;
    if (i < (size_t)NE * HD * ID) d_W1s_hi[i] = __float2half(W1[i]);
}
__global__ void conv_w2_kernel(const float* __restrict__ W2) {
    size_t i = (size_t)blockIdx.x * blockDim.x + threadIdx.x;
    if (i < (size_t)NE * ID * HD) d_W2s_hi[i] = __float2half(W2[i]);
}

// ---------------- gate: logits, top-2 softmax, assignment build ----------------
__global__ void gate_kernel(const float* __restrict__ x,
                            const float* __restrict__ gW,
                            const float* __restrict__ gb,
                            float* __restrict__ out_gw) {
    int t = blockIdx.x;
    __shared__ float logits[NE];
    int w = threadIdx.x >> 5;
    int lane = threadIdx.x & 31;
    const float* xr = x + (size_t)t * HD;
    if (w < NE) {
        const float* wr = gW + (size_t)w * HD;
        float s = 0.0f;
        for (int h = lane; h < HD; h += 32) s += xr[h] * wr[h];
        #pragma unroll
        for (int o = 16; o; o >>= 1) s += __shfl_down_sync(0xffffffffu, s, o);
        if (lane == 0) logits[w] = s + gb[w];
    }
    __syncthreads();
    if (threadIdx.x == 0) {
        int i0 = 0;
        #pragma unroll
        for (int e = 1; e < NE; e++) if (logits[e] > logits[i0]) i0 = e;
        int i1 = -1;
        #pragma unroll
        for (int e = 0; e < NE; e++) {
            if (e == i0) continue;
            if (i1 < 0 || logits[e] > logits[i1]) i1 = e;
        }
        float v0 = logits[i0], v1 = logits[i1];
        float e1 = expf(v1 - v0);
        float inv = 1.0f / (1.0f + e1);
        float p0 = inv, p1 = e1 * inv;
        float* gw = out_gw + (size_t)t * NE;
        #pragma unroll
        for (int e = 0; e < NE; e++) gw[e] = 0.0f;
        gw[i0] = p0; gw[i1] = p1;
        d_tkExpert[t * 2 + 0] = i0; d_tkProb[t * 2 + 0] = p0;
        d_tkExpert[t * 2 + 1] = i1; d_tkProb[t * 2 + 1] = p1;
        atomicAdd(&d_counts[i0], 1);
        atomicAdd(&d_counts[i1], 1);
    }
}

__global__ void offsets_kernel() {
    int acc = 0;
    for (int e = 0; e < NE; e++) { d_offsets[e] = acc; acc += d_counts[e]; }
    d_offsets[NE] = acc;
}

__global__ void scatter_kernel() {
    int a = blockIdx.x * blockDim.x + threadIdx.x;
    if (a >= NA) return;
    int e = d_tkExpert[a];
    int pos = d_offsets[e] + atomicAdd(&d_cursor[e], 1);
    d_rowToken[pos] = a >> 1;
    d_rowProb[pos]  = d_tkProb[a];
}

// ---------------- HMMA mainloop ----------------
// Tile 128(M) x 128(N), k-tile 32, 256 threads = 8 warps (2 M x 4 N),
// warp tile 64x32.  A pre-split fp16 hi/lo; B fp16 hi only.
// cp.async 4-stage pipeline, ONE __syncthreads per k-tile.
// A smem [128][32] (rows 64B, chunk swz c^((r>>1)&3));
// B smem [32][128] k-major (rows 256B, chunk swz c^(k&7)), ldmatrix.trans.
// 2-term compensation:  (Ahi + Alo) * Bhi
#define STG_A_HI 0u
#define STG_A_LO 8192u
#define STG_B_HI 16384u
#define STG_BYTES 24576u
#define NSTAGE 4
#define DSMEM_BYTES (NSTAGE * 24576)   // 96 KB

template<int KDIM>
__device__ __forceinline__ void mainloop(
    const __half* __restrict__ Ahi,
    const __half* __restrict__ Alo,
    const __half* __restrict__ Bhi,   // [KDIM][NDIM]
    int NDIM, int n0,
    const int* arow,                 // smem: 128 absolute row indices into A
    uint32_t sm,                     // u32 shared addr of dynamic smem
    float acc[4][4][4])
{
    constexpr int KT = KDIM / 32;
    int tid = threadIdx.x;
    int lane = tid & 31, warp = tid >> 5;
    int warpM = (warp >> 2) * 64;    // 2 M-warps
    int warpN = (warp & 3) * 32;     // 4 N-warps
    int g = lane >> 3;               // ldmatrix group 0..3
    int lr = lane & 7;               // row-in-group

    // ---- cp.async assignments: A 4 chunks (2 hi + 2 lo), B 2 chunks
    int acr = tid >> 1;              // A row 0..127
    int ac0 = (tid & 1) * 2;         // chunk 0 or 2
    const __half* aHiSrc = Ahi + (size_t)arow[acr] * KDIM + ac0 * 8;
    const __half* aLoSrc = Alo + (size_t)arow[acr] * KDIM + ac0 * 8;
    uint32_t aD0 = (uint32_t)(acr * 64 + (( ac0      ^ ((acr >> 1) & 3)) << 4));
    uint32_t aD1 = (uint32_t)(acr * 64 + (((ac0 + 1) ^ ((acr >> 1) & 3)) << 4));

    int bkr = tid >> 3;              // B k-row 0..31
    int bc0 = (tid & 7) * 2;         // chunk 0..14 even
    const __half* bHiSrc = Bhi + (size_t)bkr * NDIM + n0 + bc0 * 8;
    uint32_t bD0 = (uint32_t)(bkr * 256 + (( bc0      ^ (bkr & 7)) << 4));
    uint32_t bD1 = (uint32_t)(bkr * 256 + (((bc0 + 1) ^ (bkr & 7)) << 4));

    auto load_stage = [&](int kt) {
        uint32_t sb = sm + (uint32_t)(kt % NSTAGE) * STG_BYTES;
        size_t ako = (size_t)kt * 32;
        size_t bko = (size_t)kt * 32 * NDIM;
        cpasync16(sb + STG_A_HI + aD0, aHiSrc + ako);
        cpasync16(sb + STG_A_HI + aD1, aHiSrc + ako + 8);
        cpasync16(sb + STG_A_LO + aD0, aLoSrc + ako);
        cpasync16(sb + STG_A_LO + aD1, aLoSrc + ako + 8);
        cpasync16(sb + STG_B_HI + bD0, bHiSrc + bko);
        cpasync16(sb + STG_B_HI + bD1, bHiSrc + bko + 8);
    };

    auto compute_stage = [&](int s) {
        uint32_t sb = sm + (uint32_t)s * STG_BYTES;
        #pragma unroll
        for (int kk = 0; kk < 2; kk++) {
            uint32_t ah[4][4], al[4][4], bh[2][4];
            #pragma unroll
            for (int mi = 0; mi < 4; mi++) {
                int row = warpM + mi * 16 + (g & 1) * 8 + lr;
                int ch = (kk * 2 + (g >> 1)) ^ ((row >> 1) & 3);
                ldsm4(ah[mi], sb + STG_A_HI + (uint32_t)(row * 64 + ch * 16));
                ldsm4(al[mi], sb + STG_A_LO + (uint32_t)(row * 64 + ch * 16));
            }
            #pragma unroll
            for (int nh = 0; nh < 2; nh++) {
                int k = kk * 16 + (g & 1) * 8 + lr;
                int n = warpN + nh * 16 + (g >> 1) * 8;
                int ch = (n >> 3) ^ (k & 7);
                ldsm4t(bh[nh], sb + STG_B_HI + (uint32_t)(k * 256 + ch * 16));
            }
            #pragma unroll
            for (int mi = 0; mi < 4; mi++) {
                #pragma unroll
                for (int j = 0; j < 4; j++) {
                    int nh = j >> 1, o = (j & 1) * 2;
                    mma16816(acc[mi][j], ah[mi], bh[nh][o], bh[nh][o + 1]);
                    mma16816(acc[mi][j], al[mi], bh[nh][o], bh[nh][o + 1]);
                }
            }
        }
    };

    load_stage(0); cp_commit();
    load_stage(1); cp_commit();
    load_stage(2); cp_commit();

    for (int kt = 0; kt < KT; kt++) {
        cp_wait2();              // stage kt arrived
        __syncthreads();         // ...and stage slot (kt+3)%4 fully consumed
        if (kt + 3 < KT) load_stage(kt + 3);
        cp_commit();
        compute_stage(kt % NSTAGE);
    }
}

// ===================== GEMM1: h1 = gelu(x @ W1 + b1) ==========================
__global__ void __launch_bounds__(256, 2)
gemm1_hmma(const float* __restrict__ b1) {
    int e = blockIdx.z;
    int cnt = d_counts[e];
    int rowTile = blockIdx.y * 128;
    if (rowTile >= cnt) return;
    int base = d_offsets[e];
    int n0 = blockIdx.x * 128;

    extern __shared__ __align__(16) char dyn_raw[];
    uint32_t sm = (uint32_t)__cvta_generic_to_shared(dyn_raw);

    __shared__ int arow[128];
    int tid = threadIdx.x;
    if (tid < 128) {
        int r = rowTile + tid;
        arow[tid] = d_rowToken[base + min(r, cnt - 1)];
    }
    __syncthreads();

    float acc[4][4][4] = {};
    mainloop<HD>(d_x_hi, d_x_lo,
                 d_W1s_hi + (size_t)e * HD * ID,
                 ID, n0, arow, sm, acc);

    int lane = tid & 31, warp = tid >> 5;
    int warpM = (warp >> 2) * 64, warpN = (warp & 3) * 32;
    int qr = lane >> 2, qc = (lane & 3) * 2;
    const float* bb = b1 + (size_t)e * ID;
    #pragma unroll
    for (int mi = 0; mi < 4; mi++) {
        #pragma unroll
        for (int rr = 0; rr < 2; rr++) {
            int lrow = warpM + mi * 16 + rr * 8 + qr;
            int gr = rowTile + lrow;
            if (gr >= cnt) continue;
            size_t orow = (size_t)(base + gr) * ID + n0;
            #pragma unroll
            for (int j = 0; j < 4; j++) {
                int n = warpN + j * 8 + qc;
                float v0 = acc[mi][j][rr * 2]     + bb[n0 + n];
                float v1 = acc[mi][j][rr * 2 + 1] + bb[n0 + n + 1];
                float g0 = 0.5f * v0 * (1.0f + erff(v0 * 0.70710678118654752f));
                float g1 = 0.5f * v1 * (1.0f + erff(v1 * 0.70710678118654752f));
                __half h0, l0, h1v, l1v;
                split_h(g0, h0, l0); split_h(g1, h1v, l1v);
                *(uint32_t*)(d_h1_hi + orow + n) = pack_h(h0, h1v);
                *(uint32_t*)(d_h1_lo + orow + n) = pack_h(l0, l1v);
            }
        }
    }
}

// ===================== GEMM2: out += p * (h1 @ W2 + b2) =======================
__global__ void __launch_bounds__(256, 2)
gemm2_hmma(const float* __restrict__ b2, float* __restrict__ out) {
    int e = blockIdx.z;
    int cnt = d_counts[e];
    int rowTile = blockIdx.y * 128;
    if (rowTile >= cnt) return;
    int base = d_offsets[e];
    int n0 = blockIdx.x * 128;

    extern __shared__ __align__(16) char dyn_raw[];
    uint32_t sm = (uint32_t)__cvta_generic_to_shared(dyn_raw);

    __shared__ int arow[128];
    __shared__ int stok[128];
    __shared__ float sprob[128];
    int tid = threadIdx.x;
    if (tid < 128) {
        int r = rowTile + tid;
        int rc = base + min(r, cnt - 1);
        arow[tid]  = rc;
        stok[tid]  = d_rowToken[rc];
        sprob[tid] = d_rowProb[rc];
    }
    __syncthreads();

    float acc[4][4][4] = {};
    mainloop<ID>(d_h1_hi, d_h1_lo,
                 d_W2s_hi + (size_t)e * ID * HD,
                 HD, n0, arow, sm, acc);

    int lane = tid & 31, warp = tid >> 5;
    int warpM = (warp >> 2) * 64, warpN = (warp & 3) * 32;
    int qr = lane >> 2, qc = (lane & 3) * 2;
    const float* bb = b2 + (size_t)e * HD;
    #pragma unroll
    for (int mi = 0; mi < 4; mi++) {
        #pragma unroll
        for (int rr = 0; rr < 2; rr++) {
            int lrow = warpM + mi * 16 + rr * 8 + qr;
            int gr = rowTile + lrow;
            if (gr >= cnt) continue;
            int tok = stok[lrow];
            float p = sprob[lrow];
            float* od = out + (size_t)tok * HD + n0;
            #pragma unroll
            for (int j = 0; j < 4; j++) {
                int n = warpN + j * 8 + qc;
                atomicAdd(&od[n],     p * (acc[mi][j][rr * 2]     + bb[n0 + n]));
                atomicAdd(&od[n + 1], p * (acc[mi][j][rr * 2 + 1] + bb[n0 + n + 1]));
            }
        }
    }
}

// ---------------- launch ----------------
extern "C" void kernel_launch(void* const* d_in, const int* in_sizes, int n_in,
                              void* d_out, int out_size) {
    const float* x     = (const float*)d_in[0];
    const float* gateW = (const float*)d_in[1];
    const float* gateB = (const float*)d_in[2];
    const float* W1    = (const float*)d_in[3];
    const float* b1    = (const float*)d_in[4];
    const float* W2    = (const float*)d_in[5];
    const float* b2    = (const float*)d_in[6];
    float* out = (float*)d_out;                    // [TOKENS*HD]
    float* out_gw = out + (size_t)TOKENS * HD;     // [TOKENS*NE]

    cudaFuncSetAttribute(gemm1_hmma, cudaFuncAttributeMaxDynamicSharedMemorySize, DSMEM_BYTES);
    cudaFuncSetAttribute(gemm2_hmma, cudaFuncAttributeMaxDynamicSharedMemorySize, DSMEM_BYTES);

    reset_counters_kernel<<<1, 32>>>();
    zero_out_kernel<<<(TOKENS * HD + 255) / 256, 256>>>(out, TOKENS * HD);
    gate_kernel<<<TOKENS, 224>>>(x, gateW, gateB, out_gw);
    offsets_kernel<<<1, 1>>>();
    scatter_kernel<<<(NA + 255) / 256, 256>>>();
    split_x_kernel<<<(TOKENS * HD + 255) / 256, 256>>>(x);
    {
        size_t nw = (size_t)NE * HD * ID;
        int blocks = (int)((nw + 255) / 256);
        conv_w1_kernel<<<blocks, 256>>>(W1);
        conv_w2_kernel<<<blocks, 256>>>(W2);
    }

    dim3 g1(ID / 128, NA / 128, NE);   // (24, 64, 7)
    gemm1_hmma<<<g1, 256, DSMEM_BYTES>>>(b1);

    dim3 g2(HD / 128, NA / 128, NE);   // (6, 64, 7)
    gemm2_hmma<<<g2, 256, DSMEM_BYTES>>>(b2, out);
}

// round 10
// speedup vs baseline: 5.4303x; 1.4727x over previous
#include <cuda_runtime.h>
#include <cuda_fp16.h>
#include <cstdint>
#include <math.h>

#define TOKENS 4096
#define HD 768
#define ID 3072
#define NE 7
#define NA (TOKENS * 2)   // 8192 assignments (top-2)

// ---------------- device scratch (static, no allocation) ----------------
__device__ int   d_counts[NE];
__device__ int   d_offsets[NE + 1];
__device__ int   d_cursor[NE];
__device__ int   d_tkExpert[NA];
__device__ float d_tkProb[NA];
__device__ int   d_rowToken[NA];
__device__ float d_rowProb[NA];
__device__ __align__(16) __half d_x_h[(size_t)TOKENS * HD];      // 6 MB
__device__ __align__(16) __half d_W1s[(size_t)NE * HD * ID];     // 33 MB  [e][k][n]
__device__ __align__(16) __half d_W2s[(size_t)NE * ID * HD];     // 33 MB  [e][k][n]
__device__ __align__(16) __half d_h1[(size_t)NA * ID];           // 50 MB

// ---------------- helpers ----------------
__device__ __forceinline__ void mma16816(float* c, const uint32_t* a,
                                         uint32_t b0, uint32_t b1) {
    asm volatile(
        "mma.sync.aligned.m16n8k16.row.col.f32.f16.f16.f32 "
        "{%0,%1,%2,%3}, {%4,%5,%6,%7}, {%8,%9}, {%0,%1,%2,%3};"
        : "+f"(c[0]), "+f"(c[1]), "+f"(c[2]), "+f"(c[3])
        : "r"(a[0]), "r"(a[1]), "r"(a[2]), "r"(a[3]), "r"(b0), "r"(b1));
}

__device__ __forceinline__ void ldsm4(uint32_t* r, uint32_t addr) {
    asm volatile("ldmatrix.sync.aligned.m8n8.x4.shared.b16 {%0,%1,%2,%3}, [%4];"
                 : "=r"(r[0]), "=r"(r[1]), "=r"(r[2]), "=r"(r[3]) : "r"(addr));
}
__device__ __forceinline__ void ldsm4t(uint32_t* r, uint32_t addr) {
    asm volatile("ldmatrix.sync.aligned.m8n8.x4.trans.shared.b16 {%0,%1,%2,%3}, [%4];"
                 : "=r"(r[0]), "=r"(r[1]), "=r"(r[2]), "=r"(r[3]) : "r"(addr));
}

__device__ __forceinline__ void cpasync16(uint32_t dst, const void* src) {
    asm volatile("cp.async.cg.shared.global [%0], [%1], 16;"
                 :: "r"(dst), "l"(src) : "memory");
}
__device__ __forceinline__ void cp_commit() {
    asm volatile("cp.async.commit_group;" ::: "memory");
}
__device__ __forceinline__ void cp_wait2() {
    asm volatile("cp.async.wait_group 2;" ::: "memory");
}

__device__ __forceinline__ uint32_t pack_h(__half a, __half b) {
    __half2 t; t.x = a; t.y = b;
    uint32_t r; memcpy(&r, &t, 4); return r;
}

// ---------------- small utility kernels ----------------
__global__ void reset_counters_kernel() {
    int i = threadIdx.x;
    if (i < NE) { d_counts[i] = 0; d_cursor[i] = 0; }
}

__global__ void zero_out_kernel(float* out, int n) {
    int i = blockIdx.x * blockDim.x + threadIdx.x;
    if (i < n) out[i] = 0.0f;
}

__global__ void conv_x_kernel(const float* __restrict__ x) {
    int i = blockIdx.x * blockDim.x + threadIdx.x;
    if (i < TOKENS * HD) d_x_h[i] = __float2half(x[i]);
}

__global__ void conv_w1_kernel(const float* __restrict__ W1) {
    size_t i = (size_t)blockIdx.x * blockDim.x + threadIdx.x;
    if (i < (size_t)NE * HD * ID) d_W1s[i] = __float2half(W1[i]);
}
__global__ void conv_w2_kernel(const float* __restrict__ W2) {
    size_t i = (size_t)blockIdx.x * blockDim.x + threadIdx.x;
    if (i < (size_t)NE * ID * HD) d_W2s[i] = __float2half(W2[i]);
}

// ---------------- gate: logits, top-2 softmax, assignment build ----------------
__global__ void gate_kernel(const float* __restrict__ x,
                            const float* __restrict__ gW,
                            const float* __restrict__ gb,
                            float* __restrict__ out_gw) {
    int t = blockIdx.x;
    __shared__ float logits[NE];
    int w = threadIdx.x >> 5;
    int lane = threadIdx.x & 31;
    const float* xr = x + (size_t)t * HD;
    if (w < NE) {
        const float* wr = gW + (size_t)w * HD;
        float s = 0.0f;
        for (int h = lane; h < HD; h += 32) s += xr[h] * wr[h];
        #pragma unroll
        for (int o = 16; o; o >>= 1) s += __shfl_down_sync(0xffffffffu, s, o);
        if (lane == 0) logits[w] = s + gb[w];
    }
    __syncthreads();
    if (threadIdx.x == 0) {
        int i0 = 0;
        #pragma unroll
        for (int e = 1; e < NE; e++) if (logits[e] > logits[i0]) i0 = e;
        int i1 = -1;
        #pragma unroll
        for (int e = 0; e < NE; e++) {
            if (e == i0) continue;
            if (i1 < 0 || logits[e] > logits[i1]) i1 = e;
        }
        float v0 = logits[i0], v1 = logits[i1];
        float e1 = expf(v1 - v0);
        float inv = 1.0f / (1.0f + e1);
        float p0 = inv, p1 = e1 * inv;
        float* gw = out_gw + (size_t)t * NE;
        #pragma unroll
        for (int e = 0; e < NE; e++) gw[e] = 0.0f;
        gw[i0] = p0; gw[i1] = p1;
        d_tkExpert[t * 2 + 0] = i0; d_tkProb[t * 2 + 0] = p0;
        d_tkExpert[t * 2 + 1] = i1; d_tkProb[t * 2 + 1] = p1;
        atomicAdd(&d_counts[i0], 1);
        atomicAdd(&d_counts[i1], 1);
    }
}

__global__ void offsets_kernel() {
    int acc = 0;
    for (int e = 0; e < NE; e++) { d_offsets[e] = acc; acc += d_counts[e]; }
    d_offsets[NE] = acc;
}

__global__ void scatter_kernel() {
    int a = blockIdx.x * blockDim.x + threadIdx.x;
    if (a >= NA) return;
    int e = d_tkExpert[a];
    int pos = d_offsets[e] + atomicAdd(&d_cursor[e], 1);
    d_rowToken[pos] = a >> 1;
    d_rowProb[pos]  = d_tkProb[a];
}

// ---------------- HMMA mainloop ----------------
// Tile 128(M) x 128(N), k-tile 32, 256 threads = 8 warps (2 M x 4 N),
// warp tile 64x32.  A and B plain fp16 (single term).
// cp.async 4-stage pipeline, one __syncthreads per k-tile.
// A smem [128][32] (rows 64B, chunk swz c^((r>>1)&3));
// B smem [32][128] k-major (rows 256B, chunk swz c^(k&7)), ldmatrix.trans.
#define STG_A 0u
#define STG_B 8192u
#define STG_BYTES 16384u
#define NSTAGE 4
#define DSMEM_BYTES (NSTAGE * 16384)   // 64 KB

template<int KDIM>
__device__ __forceinline__ void mainloop(
    const __half* __restrict__ A,     // [rows][KDIM] fp16
    const __half* __restrict__ B,     // [KDIM][NDIM] fp16
    int NDIM, int n0,
    const int* arow,                  // smem: 128 absolute row indices into A
    uint32_t sm,                      // u32 shared addr of dynamic smem
    float acc[4][4][4])
{
    constexpr int KT = KDIM / 32;
    int tid = threadIdx.x;
    int lane = tid & 31, warp = tid >> 5;
    int warpM = (warp >> 2) * 64;    // 2 M-warps
    int warpN = (warp & 3) * 32;     // 4 N-warps
    int g = lane >> 3;               // ldmatrix group 0..3
    int lr = lane & 7;               // row-in-group

    // ---- cp.async assignments: A 2 chunks, B 2 chunks per thread
    int acr = tid >> 1;              // A row 0..127
    int ac0 = (tid & 1) * 2;         // chunk 0 or 2
    const __half* aSrc = A + (size_t)arow[acr] * KDIM + ac0 * 8;
    uint32_t aD0 = (uint32_t)(acr * 64 + (( ac0      ^ ((acr >> 1) & 3)) << 4));
    uint32_t aD1 = (uint32_t)(acr * 64 + (((ac0 + 1) ^ ((acr >> 1) & 3)) << 4));

    int bkr = tid >> 3;              // B k-row 0..31
    int bc0 = (tid & 7) * 2;         // chunk 0..14 even
    const __half* bSrc = B + (size_t)bkr * NDIM + n0 + bc0 * 8;
    uint32_t bD0 = (uint32_t)(bkr * 256 + (( bc0      ^ (bkr & 7)) << 4));
    uint32_t bD1 = (uint32_t)(bkr * 256 + (((bc0 + 1) ^ (bkr & 7)) << 4));

    auto load_stage = [&](int kt) {
        uint32_t sb = sm + (uint32_t)(kt % NSTAGE) * STG_BYTES;
        size_t ako = (size_t)kt * 32;
        size_t bko = (size_t)kt * 32 * NDIM;
        cpasync16(sb + STG_A + aD0, aSrc + ako);
        cpasync16(sb + STG_A + aD1, aSrc + ako + 8);
        cpasync16(sb + STG_B + bD0, bSrc + bko);
        cpasync16(sb + STG_B + bD1, bSrc + bko + 8);
    };

    auto compute_stage = [&](int s) {
        uint32_t sb = sm + (uint32_t)s * STG_BYTES;
        #pragma unroll
        for (int kk = 0; kk < 2; kk++) {
            uint32_t a[4][4], bh[2][4];
            #pragma unroll
            for (int mi = 0; mi < 4; mi++) {
                int row = warpM + mi * 16 + (g & 1) * 8 + lr;
                int ch = (kk * 2 + (g >> 1)) ^ ((row >> 1) & 3);
                ldsm4(a[mi], sb + STG_A + (uint32_t)(row * 64 + ch * 16));
            }
            #pragma unroll
            for (int nh = 0; nh < 2; nh++) {
                int k = kk * 16 + (g & 1) * 8 + lr;
                int n = warpN + nh * 16 + (g >> 1) * 8;
                int ch = (n >> 3) ^ (k & 7);
                ldsm4t(bh[nh], sb + STG_B + (uint32_t)(k * 256 + ch * 16));
            }
            #pragma unroll
            for (int mi = 0; mi < 4; mi++) {
                #pragma unroll
                for (int j = 0; j < 4; j++) {
                    int nh = j >> 1, o = (j & 1) * 2;
                    mma16816(acc[mi][j], a[mi], bh[nh][o], bh[nh][o + 1]);
                }
            }
        }
    };

    load_stage(0); cp_commit();
    load_stage(1); cp_commit();
    load_stage(2); cp_commit();

    for (int kt = 0; kt < KT; kt++) {
        cp_wait2();              // stage kt arrived
        __syncthreads();         // ...and stage slot (kt+3)%4 fully consumed
        if (kt + 3 < KT) load_stage(kt + 3);
        cp_commit();
        compute_stage(kt % NSTAGE);
    }
}

// ===================== GEMM1: h1 = gelu(x @ W1 + b1) ==========================
__global__ void __launch_bounds__(256, 2)
gemm1_hmma(const float* __restrict__ b1) {
    int e = blockIdx.z;
    int cnt = d_counts[e];
    int rowTile = blockIdx.y * 128;
    if (rowTile >= cnt) return;
    int base = d_offsets[e];
    int n0 = blockIdx.x * 128;

    extern __shared__ __align__(16) char dyn_raw[];
    uint32_t sm = (uint32_t)__cvta_generic_to_shared(dyn_raw);

    __shared__ int arow[128];
    int tid = threadIdx.x;
    if (tid < 128) {
        int r = rowTile + tid;
        arow[tid] = d_rowToken[base + min(r, cnt - 1)];
    }
    __syncthreads();

    float acc[4][4][4] = {};
    mainloop<HD>(d_x_h, d_W1s + (size_t)e * HD * ID,
                 ID, n0, arow, sm, acc);

    int lane = tid & 31, warp = tid >> 5;
    int warpM = (warp >> 2) * 64, warpN = (warp & 3) * 32;
    int qr = lane >> 2, qc = (lane & 3) * 2;
    const float* bb = b1 + (size_t)e * ID;
    #pragma unroll
    for (int mi = 0; mi < 4; mi++) {
        #pragma unroll
        for (int rr = 0; rr < 2; rr++) {
            int lrow = warpM + mi * 16 + rr * 8 + qr;
            int gr = rowTile + lrow;
            if (gr >= cnt) continue;
            size_t orow = (size_t)(base + gr) * ID + n0;
            #pragma unroll
            for (int j = 0; j < 4; j++) {
                int n = warpN + j * 8 + qc;
                float v0 = acc[mi][j][rr * 2]     + bb[n0 + n];
                float v1 = acc[mi][j][rr * 2 + 1] + bb[n0 + n + 1];
                float g0 = 0.5f * v0 * (1.0f + erff(v0 * 0.70710678118654752f));
                float g1 = 0.5f * v1 * (1.0f + erff(v1 * 0.70710678118654752f));
                *(uint32_t*)(d_h1 + orow + n) =
                    pack_h(__float2half(g0), __float2half(g1));
            }
        }
    }
}

// ===================== GEMM2: out += p * (h1 @ W2 + b2) =======================
__global__ void __launch_bounds__(256, 2)
gemm2_hmma(const float* __restrict__ b2, float* __restrict__ out) {
    int e = blockIdx.z;
    int cnt = d_counts[e];
    int rowTile = blockIdx.y * 128;
    if (rowTile >= cnt) return;
    int base = d_offsets[e];
    int n0 = blockIdx.x * 128;

    extern __shared__ __align__(16) char dyn_raw[];
    uint32_t sm = (uint32_t)__cvta_generic_to_shared(dyn_raw);

    __shared__ int arow[128];
    __shared__ int stok[128];
    __shared__ float sprob[128];
    int tid = threadIdx.x;
    if (tid < 128) {
        int r = rowTile + tid;
        int rc = base + min(r, cnt - 1);
        arow[tid]  = rc;
        stok[tid]  = d_rowToken[rc];
        sprob[tid] = d_rowProb[rc];
    }
    __syncthreads();

    float acc[4][4][4] = {};
    mainloop<ID>(d_h1, d_W2s + (size_t)e * ID * HD,
                 HD, n0, arow, sm, acc);

    int lane = tid & 31, warp = tid >> 5;
    int warpM = (warp >> 2) * 64, warpN = (warp & 3) * 32;
    int qr = lane >> 2, qc = (lane & 3) * 2;
    const float* bb = b2 + (size_t)e * HD;
    #pragma unroll
    for (int mi = 0; mi < 4; mi++) {
        #pragma unroll
        for (int rr = 0; rr < 2; rr++) {
            int lrow = warpM + mi * 16 + rr * 8 + qr;
            int gr = rowTile + lrow;
            if (gr >= cnt) continue;
            int tok = stok[lrow];
            float p = sprob[lrow];
            float* od = out + (size_t)tok * HD + n0;
            #pragma unroll
            for (int j = 0; j < 4; j++) {
                int n = warpN + j * 8 + qc;
                atomicAdd(&od[n],     p * (acc[mi][j][rr * 2]     + bb[n0 + n]));
                atomicAdd(&od[n + 1], p * (acc[mi][j][rr * 2 + 1] + bb[n0 + n + 1]));
            }
        }
    }
}

// ---------------- launch ----------------
extern "C" void kernel_launch(void* const* d_in, const int* in_sizes, int n_in,
                              void* d_out, int out_size) {
    const float* x     = (const float*)d_in[0];
    const float* gateW = (const float*)d_in[1];
    const float* gateB = (const float*)d_in[2];
    const float* W1    = (const float*)d_in[3];
    const float* b1    = (const float*)d_in[4];
    const float* W2    = (const float*)d_in[5];
    const float* b2    = (const float*)d_in[6];
    float* out = (float*)d_out;                    // [TOKENS*HD]
    float* out_gw = out + (size_t)TOKENS * HD;     // [TOKENS*NE]

    cudaFuncSetAttribute(gemm1_hmma, cudaFuncAttributeMaxDynamicSharedMemorySize, DSMEM_BYTES);
    cudaFuncSetAttribute(gemm2_hmma, cudaFuncAttributeMaxDynamicSharedMemorySize, DSMEM_BYTES);

    reset_counters_kernel<<<1, 32>>>();
    zero_out_kernel<<<(TOKENS * HD + 255) / 256, 256>>>(out, TOKENS * HD);
    gate_kernel<<<TOKENS, 224>>>(x, gateW, gateB, out_gw);
    offsets_kernel<<<1, 1>>>();
    scatter_kernel<<<(NA + 255) / 256, 256>>>();
    conv_x_kernel<<<(TOKENS * HD + 255) / 256, 256>>>(x);
    {
        size_t nw = (size_t)NE * HD * ID;
        int blocks = (int)((nw + 255) / 256);
        conv_w1_kernel<<<blocks, 256>>>(W1);
        conv_w2_kernel<<<blocks, 256>>>(W2);
    }

    dim3 g1(ID / 128, NA / 128, NE);   // (24, 64, 7)
    gemm1_hmma<<<g1, 256, DSMEM_BYTES>>>(b1);

    dim3 g2(HD / 128, NA / 128, NE);   // (6, 64, 7)
    gemm2_hmma<<<g2, 256, DSMEM_BYTES>>>(b2, out);
}

// round 11
// speedup vs baseline: 5.6776x; 1.0455x over previous
#include <cuda_runtime.h>
#include <cuda_fp16.h>
#include <cstdint>
#include <math.h>

#define TOKENS 4096
#define HD 768
#define ID 3072
#define NE 7
#define NA (TOKENS * 2)   // 8192 assignments (top-2)

// ---------------- device scratch (static, no allocation) ----------------
__device__ int   d_counts[NE];
__device__ int   d_offsets[NE + 1];
__device__ int   d_cursor[NE];
__device__ int   d_tkExpert[NA];
__device__ float d_tkProb[NA];
__device__ int   d_rowToken[NA];
__device__ float d_rowProb[NA];
__device__ __align__(16) __half d_x_h[(size_t)TOKENS * HD];      // 6 MB
__device__ __align__(16) __half d_W1s[(size_t)NE * HD * ID];     // 33 MB  [e][k][n]
__device__ __align__(16) __half d_W2s[(size_t)NE * ID * HD];     // 33 MB  [e][k][n]
__device__ __align__(16) __half d_h1[(size_t)NA * ID];           // 50 MB

// ---------------- helpers ----------------
__device__ __forceinline__ void mma16816(float* c, const uint32_t* a,
                                         uint32_t b0, uint32_t b1) {
    asm volatile(
        "mma.sync.aligned.m16n8k16.row.col.f32.f16.f16.f32 "
        "{%0,%1,%2,%3}, {%4,%5,%6,%7}, {%8,%9}, {%0,%1,%2,%3};"
        : "+f"(c[0]), "+f"(c[1]), "+f"(c[2]), "+f"(c[3])
        : "r"(a[0]), "r"(a[1]), "r"(a[2]), "r"(a[3]), "r"(b0), "r"(b1));
}

__device__ __forceinline__ void ldsm4(uint32_t* r, uint32_t addr) {
    asm volatile("ldmatrix.sync.aligned.m8n8.x4.shared.b16 {%0,%1,%2,%3}, [%4];"
                 : "=r"(r[0]), "=r"(r[1]), "=r"(r[2]), "=r"(r[3]) : "r"(addr));
}
__device__ __forceinline__ void ldsm4t(uint32_t* r, uint32_t addr) {
    asm volatile("ldmatrix.sync.aligned.m8n8.x4.trans.shared.b16 {%0,%1,%2,%3}, [%4];"
                 : "=r"(r[0]), "=r"(r[1]), "=r"(r[2]), "=r"(r[3]) : "r"(addr));
}

__device__ __forceinline__ void cpasync16(uint32_t dst, const void* src) {
    asm volatile("cp.async.cg.shared.global [%0], [%1], 16;"
                 :: "r"(dst), "l"(src) : "memory");
}
__device__ __forceinline__ void cp_commit() {
    asm volatile("cp.async.commit_group;" ::: "memory");
}
__device__ __forceinline__ void cp_wait1() {
    asm volatile("cp.async.wait_group 1;" ::: "memory");
}

__device__ __forceinline__ uint32_t pack_h(__half a, __half b) {
    __half2 t; t.x = a; t.y = b;
    uint32_t r; memcpy(&r, &t, 4); return r;
}

// ---------------- small utility kernels ----------------
__global__ void reset_counters_kernel() {
    int i = threadIdx.x;
    if (i < NE) { d_counts[i] = 0; d_cursor[i] = 0; }
}

__global__ void zero_out_kernel(float* out, int n) {
    int i = blockIdx.x * blockDim.x + threadIdx.x;
    if (i < n) out[i] = 0.0f;
}

// vectorized fp32 -> fp16 converters (8 elements per thread)
__device__ __forceinline__ void conv8(const float* __restrict__ src,
                                      __half* __restrict__ dst, size_t i) {
    float4 v0 = *(const float4*)(src + i);
    float4 v1 = *(const float4*)(src + i + 4);
    uint4 o;
    o.x = pack_h(__float2half(v0.x), __float2half(v0.y));
    o.y = pack_h(__float2half(v0.z), __float2half(v0.w));
    o.z = pack_h(__float2half(v1.x), __float2half(v1.y));
    o.w = pack_h(__float2half(v1.z), __float2half(v1.w));
    *(uint4*)(dst + i) = o;
}

__global__ void conv_x_kernel(const float* __restrict__ x) {
    size_t i = ((size_t)blockIdx.x * blockDim.x + threadIdx.x) * 8;
    if (i < (size_t)TOKENS * HD) conv8(x, d_x_h, i);
}
__global__ void conv_w1_kernel(const float* __restrict__ W1) {
    size_t i = ((size_t)blockIdx.x * blockDim.x + threadIdx.x) * 8;
    if (i < (size_t)NE * HD * ID) conv8(W1, d_W1s, i);
}
__global__ void conv_w2_kernel(const float* __restrict__ W2) {
    size_t i = ((size_t)blockIdx.x * blockDim.x + threadIdx.x) * 8;
    if (i < (size_t)NE * ID * HD) conv8(W2, d_W2s, i);
}

// ---------------- gate: logits, top-2 softmax, assignment build ----------------
__global__ void gate_kernel(const float* __restrict__ x,
                            const float* __restrict__ gW,
                            const float* __restrict__ gb,
                            float* __restrict__ out_gw) {
    int t = blockIdx.x;
    __shared__ float logits[NE];
    int w = threadIdx.x >> 5;
    int lane = threadIdx.x & 31;
    const float* xr = x + (size_t)t * HD;
    if (w < NE) {
        const float* wr = gW + (size_t)w * HD;
        float s = 0.0f;
        for (int h = lane; h < HD; h += 32) s += xr[h] * wr[h];
        #pragma unroll
        for (int o = 16; o; o >>= 1) s += __shfl_down_sync(0xffffffffu, s, o);
        if (lane == 0) logits[w] = s + gb[w];
    }
    __syncthreads();
    if (threadIdx.x == 0) {
        int i0 = 0;
        #pragma unroll
        for (int e = 1; e < NE; e++) if (logits[e] > logits[i0]) i0 = e;
        int i1 = -1;
        #pragma unroll
        for (int e = 0; e < NE; e++) {
            if (e == i0) continue;
            if (i1 < 0 || logits[e] > logits[i1]) i1 = e;
        }
        float v0 = logits[i0], v1 = logits[i1];
        float e1 = expf(v1 - v0);
        float inv = 1.0f / (1.0f + e1);
        float p0 = inv, p1 = e1 * inv;
        float* gw = out_gw + (size_t)t * NE;
        #pragma unroll
        for (int e = 0; e < NE; e++) gw[e] = 0.0f;
        gw[i0] = p0; gw[i1] = p1;
        d_tkExpert[t * 2 + 0] = i0; d_tkProb[t * 2 + 0] = p0;
        d_tkExpert[t * 2 + 1] = i1; d_tkProb[t * 2 + 1] = p1;
        atomicAdd(&d_counts[i0], 1);
        atomicAdd(&d_counts[i1], 1);
    }
}

__global__ void offsets_kernel() {
    int acc = 0;
    for (int e = 0; e < NE; e++) { d_offsets[e] = acc; acc += d_counts[e]; }
    d_offsets[NE] = acc;
}

__global__ void scatter_kernel() {
    int a = blockIdx.x * blockDim.x + threadIdx.x;
    if (a >= NA) return;
    int e = d_tkExpert[a];
    int pos = d_offsets[e] + atomicAdd(&d_cursor[e], 1);
    d_rowToken[pos] = a >> 1;
    d_rowProb[pos]  = d_tkProb[a];
}

// ---------------- HMMA mainloop ----------------
// Tile 128(M) x 128(N), k-tile 64, 256 threads = 8 warps (2 M x 4 N),
// warp tile 64x32.  Plain fp16 operands.
// cp.async 3-stage pipeline (32 KB/stage), one __syncthreads per k-tile.
// A smem [128][64] fp16: rows 128B = 8 chunks of 16B, phys chunk = c ^ (r&7).
// B smem [64][128] fp16 k-major: rows 256B = 16 chunks, phys = c ^ (k&7).
#define STG_A 0u
#define STG_B 16384u
#define STG_BYTES 32768u
#define NSTAGE 3
#define DSMEM_BYTES (NSTAGE * 32768)   // 96 KB

template<int KDIM>
__device__ __forceinline__ void mainloop(
    const __half* __restrict__ A,     // [rows][KDIM] fp16
    const __half* __restrict__ B,     // [KDIM][NDIM] fp16
    int NDIM, int n0,
    const int* arow,                  // smem: 128 absolute row indices into A
    uint32_t sm,                      // u32 shared addr of dynamic smem
    float acc[4][4][4])
{
    constexpr int KT = KDIM / 64;
    int tid = threadIdx.x;
    int lane = tid & 31, warp = tid >> 5;
    int warpM = (warp >> 2) * 64;    // 2 M-warps
    int warpN = (warp & 3) * 32;     // 4 N-warps
    int g = lane >> 3;               // ldmatrix group 0..3
    int lr = lane & 7;               // row-in-group

    // ---- cp.async assignments: A 4 chunks, B 4 chunks per thread
    int acr = tid >> 1;              // A row 0..127
    int acb = (tid & 1) * 4;         // chunk base 0 or 4
    const __half* aSrc = A + (size_t)arow[acr] * KDIM + acb * 8;
    uint32_t aD[4];
    #pragma unroll
    for (int i = 0; i < 4; i++)
        aD[i] = (uint32_t)(acr * 128 + (((acb + i) ^ (acr & 7)) << 4));

    int bkr = tid >> 2;              // B k-row 0..63
    int bcb = (tid & 3) * 4;         // chunk base 0,4,8,12
    const __half* bSrc = B + (size_t)bkr * NDIM + n0 + bcb * 8;
    uint32_t bD[4];
    #pragma unroll
    for (int i = 0; i < 4; i++)
        bD[i] = (uint32_t)(bkr * 256 + (((bcb + i) ^ (bkr & 7)) << 4));

    auto load_stage = [&](int kt) {
        uint32_t sb = sm + (uint32_t)(kt % NSTAGE) * STG_BYTES;
        size_t ako = (size_t)kt * 64;
        size_t bko = (size_t)kt * 64 * NDIM;
        #pragma unroll
        for (int i = 0; i < 4; i++)
            cpasync16(sb + STG_A + aD[i], aSrc + ako + i * 8);
        #pragma unroll
        for (int i = 0; i < 4; i++)
            cpasync16(sb + STG_B + bD[i], bSrc + bko + i * 8);
    };

    auto compute_stage = [&](int s) {
        uint32_t sb = sm + (uint32_t)s * STG_BYTES;
        #pragma unroll
        for (int kk = 0; kk < 4; kk++) {
            uint32_t a[4][4], bh[2][4];
            #pragma unroll
            for (int mi = 0; mi < 4; mi++) {
                int row = warpM + mi * 16 + (g & 1) * 8 + lr;
                int ch = (kk * 2 + (g >> 1)) ^ (row & 7);
                ldsm4(a[mi], sb + STG_A + (uint32_t)(row * 128 + ch * 16));
            }
            #pragma unroll
            for (int nh = 0; nh < 2; nh++) {
                int k = kk * 16 + (g & 1) * 8 + lr;
                int n = warpN + nh * 16 + (g >> 1) * 8;
                int ch = (n >> 3) ^ (k & 7);
                ldsm4t(bh[nh], sb + STG_B + (uint32_t)(k * 256 + ch * 16));
            }
            #pragma unroll
            for (int mi = 0; mi < 4; mi++) {
                #pragma unroll
                for (int j = 0; j < 4; j++) {
                    int nh = j >> 1, o = (j & 1) * 2;
                    mma16816(acc[mi][j], a[mi], bh[nh][o], bh[nh][o + 1]);
                }
            }
        }
    };

    load_stage(0); cp_commit();
    load_stage(1); cp_commit();

    for (int kt = 0; kt < KT; kt++) {
        cp_wait1();              // stage kt arrived
        __syncthreads();         // ...and stage slot (kt+2)%3 fully consumed
        if (kt + 2 < KT) load_stage(kt + 2);
        cp_commit();
        compute_stage(kt % NSTAGE);
    }
}

// ===================== GEMM1: h1 = gelu(x @ W1 + b1) ==========================
__global__ void __launch_bounds__(256, 2)
gemm1_hmma(const float* __restrict__ b1) {
    int e = blockIdx.z;
    int cnt = d_counts[e];
    int rowTile = blockIdx.y * 128;
    if (rowTile >= cnt) return;
    int base = d_offsets[e];
    int n0 = blockIdx.x * 128;

    extern __shared__ __align__(16) char dyn_raw[];
    uint32_t sm = (uint32_t)__cvta_generic_to_shared(dyn_raw);

    __shared__ int arow[128];
    int tid = threadIdx.x;
    if (tid < 128) {
        int r = rowTile + tid;
        arow[tid] = d_rowToken[base + min(r, cnt - 1)];
    }
    __syncthreads();

    float acc[4][4][4] = {};
    mainloop<HD>(d_x_h, d_W1s + (size_t)e * HD * ID,
                 ID, n0, arow, sm, acc);

    int lane = tid & 31, warp = tid >> 5;
    int warpM = (warp >> 2) * 64, warpN = (warp & 3) * 32;
    int qr = lane >> 2, qc = (lane & 3) * 2;
    const float* bb = b1 + (size_t)e * ID;
    #pragma unroll
    for (int mi = 0; mi < 4; mi++) {
        #pragma unroll
        for (int rr = 0; rr < 2; rr++) {
            int lrow = warpM + mi * 16 + rr * 8 + qr;
            int gr = rowTile + lrow;
            if (gr >= cnt) continue;
            size_t orow = (size_t)(base + gr) * ID + n0;
            #pragma unroll
            for (int j = 0; j < 4; j++) {
                int n = warpN + j * 8 + qc;
                float v0 = acc[mi][j][rr * 2]     + bb[n0 + n];
                float v1 = acc[mi][j][rr * 2 + 1] + bb[n0 + n + 1];
                float g0 = 0.5f * v0 * (1.0f + erff(v0 * 0.70710678118654752f));
                float g1 = 0.5f * v1 * (1.0f + erff(v1 * 0.70710678118654752f));
                *(uint32_t*)(d_h1 + orow + n) =
                    pack_h(__float2half(g0), __float2half(g1));
            }
        }
    }
}

// ===================== GEMM2: out += p * (h1 @ W2 + b2) =======================
__global__ void __launch_bounds__(256, 2)
gemm2_hmma(const float* __restrict__ b2, float* __restrict__ out) {
    int e = blockIdx.z;
    int cnt = d_counts[e];
    int rowTile = blockIdx.y * 128;
    if (rowTile >= cnt) return;
    int base = d_offsets[e];
    int n0 = blockIdx.x * 128;

    extern __shared__ __align__(16) char dyn_raw[];
    uint32_t sm = (uint32_t)__cvta_generic_to_shared(dyn_raw);

    __shared__ int arow[128];
    __shared__ int stok[128];
    __shared__ float sprob[128];
    int tid = threadIdx.x;
    if (tid < 128) {
        int r = rowTile + tid;
        int rc = base + min(r, cnt - 1);
        arow[tid]  = rc;
        stok[tid]  = d_rowToken[rc];
        sprob[tid] = d_rowProb[rc];
    }
    __syncthreads();

    float acc[4][4][4] = {};
    mainloop<ID>(d_h1, d_W2s + (size_t)e * ID * HD,
                 HD, n0, arow, sm, acc);

    int lane = tid & 31, warp = tid >> 5;
    int warpM = (warp >> 2) * 64, warpN = (warp & 3) * 32;
    int qr = lane >> 2, qc = (lane & 3) * 2;
    const float* bb = b2 + (size_t)e * HD;
    #pragma unroll
    for (int mi = 0; mi < 4; mi++) {
        #pragma unroll
        for (int rr = 0; rr < 2; rr++) {
            int lrow = warpM + mi * 16 + rr * 8 + qr;
            int gr = rowTile + lrow;
            if (gr >= cnt) continue;
            int tok = stok[lrow];
            float p = sprob[lrow];
            float* od = out + (size_t)tok * HD + n0;
            #pragma unroll
            for (int j = 0; j < 4; j++) {
                int n = warpN + j * 8 + qc;
                atomicAdd(&od[n],     p * (acc[mi][j][rr * 2]     + bb[n0 + n]));
                atomicAdd(&od[n + 1], p * (acc[mi][j][rr * 2 + 1] + bb[n0 + n + 1]));
            }
        }
    }
}

// ---------------- launch ----------------
extern "C" void kernel_launch(void* const* d_in, const int* in_sizes, int n_in,
                              void* d_out, int out_size) {
    const float* x     = (const float*)d_in[0];
    const float* gateW = (const float*)d_in[1];
    const float* gateB = (const float*)d_in[2];
    const float* W1    = (const float*)d_in[3];
    const float* b1    = (const float*)d_in[4];
    const float* W2    = (const float*)d_in[5];
    const float* b2    = (const float*)d_in[6];
    float* out = (float*)d_out;                    // [TOKENS*HD]
    float* out_gw = out + (size_t)TOKENS * HD;     // [TOKENS*NE]

    cudaFuncSetAttribute(gemm1_hmma, cudaFuncAttributeMaxDynamicSharedMemorySize, DSMEM_BYTES);
    cudaFuncSetAttribute(gemm2_hmma, cudaFuncAttributeMaxDynamicSharedMemorySize, DSMEM_BYTES);

    reset_counters_kernel<<<1, 32>>>();
    zero_out_kernel<<<(TOKENS * HD + 255) / 256, 256>>>(out, TOKENS * HD);
    gate_kernel<<<TOKENS, 224>>>(x, gateW, gateB, out_gw);
    offsets_kernel<<<1, 1>>>();
    scatter_kernel<<<(NA + 255) / 256, 256>>>();
    conv_x_kernel<<<(TOKENS * HD / 8 + 255) / 256, 256>>>(x);
    {
        size_t nw = (size_t)NE * HD * ID;
        int blocks = (int)((nw / 8 + 255) / 256);
        conv_w1_kernel<<<blocks, 256>>>(W1);
        conv_w2_kernel<<<blocks, 256>>>(W2);
    }

    dim3 g1(ID / 128, NA / 128, NE);   // (24, 64, 7)
    gemm1_hmma<<<g1, 256, DSMEM_BYTES>>>(b1);

    dim3 g2(HD / 128, NA / 128, NE);   // (6, 64, 7)
    gemm2_hmma<<<g2, 256, DSMEM_BYTES>>>(b2, out);
}